// round 5
// baseline (speedup 1.0000x reference)
#include <cuda_runtime.h>
#include <cuda_bf16.h>
#include <math.h>
#include <stdint.h>

#define N_NODES 50000
#define N_EDGES 800000
#define N_GRAPHS 512
#define IN_DIM 126
#define DIMH 128
#define LIN1_DIM 64
#define BN_EPS 1e-5f

// ---------------- device scratch ----------------
__device__ float g_feat[N_NODES * DIMH];
__device__ float g_out[N_NODES * DIMH];
__device__ int   g_cnt[N_NODES];
__device__ int   g_off[N_NODES + 1];
__device__ int   g_cur[N_NODES];
__device__ int   g_srcs[N_EDGES];
__device__ float g_pool[N_GRAPHS * DIMH];

// ---------------- utility kernels ----------------
__global__ void zero_int_kernel(int* p, int n) {
    int i = blockIdx.x * blockDim.x + threadIdx.x;
    if (i < n) p[i] = 0;
}
__global__ void zero_float_kernel(float* p, int n) {
    int i = blockIdx.x * blockDim.x + threadIdx.x;
    if (i < n) p[i] = 0.0f;
}
__global__ void count_kernel(const int* __restrict__ dst) {
    int i = blockIdx.x * blockDim.x + threadIdx.x;
    if (i < N_EDGES) atomicAdd(&g_cnt[dst[i]], 1);
}

// exclusive scan over g_cnt -> g_off and g_cur (single block)
__global__ void scan_kernel(int n) {
    __shared__ int warp_sums[32];
    __shared__ int s_carry;
    int tid = threadIdx.x;
    int lane = tid & 31, wid = tid >> 5;
    const int NW = 32;
    if (tid == 0) s_carry = 0;
    __syncthreads();
    for (int base = 0; base < n; base += blockDim.x) {
        int i = base + tid;
        int v = (i < n) ? g_cnt[i] : 0;
        int x = v;
        #pragma unroll
        for (int o = 1; o < 32; o <<= 1) {
            int t = __shfl_up_sync(0xFFFFFFFFu, x, o);
            if (lane >= o) x += t;
        }
        if (lane == 31) warp_sums[wid] = x;
        __syncthreads();
        if (wid == 0) {
            int s = (lane < NW) ? warp_sums[lane] : 0;
            #pragma unroll
            for (int o = 1; o < 32; o <<= 1) {
                int t = __shfl_up_sync(0xFFFFFFFFu, s, o);
                if (lane >= o) s += t;
            }
            warp_sums[lane] = s;
        }
        __syncthreads();
        int excl = s_carry + x - v + (wid > 0 ? warp_sums[wid - 1] : 0);
        if (i < n) { g_off[i] = excl; g_cur[i] = excl; }
        __syncthreads();
        if (tid == 0) s_carry += warp_sums[NW - 1];
        __syncthreads();
    }
    if (threadIdx.x == 0) g_off[n] = s_carry;
}

__global__ void scatter_kernel(const int* __restrict__ src, const int* __restrict__ dst) {
    int i = blockIdx.x * blockDim.x + threadIdx.x;
    if (i < N_EDGES) {
        int p = atomicAdd(&g_cur[dst[i]], 1);
        g_srcs[p] = src[i];
    }
}

__global__ void pad_x_kernel(const float* __restrict__ x) {
    int i = blockIdx.x * blockDim.x + threadIdx.x;
    if (i < N_NODES * DIMH) {
        int n = i >> 7, d = i & 127;
        g_feat[i] = (d < IN_DIM) ? x[n * IN_DIM + d] : 0.0f;
    }
}

// ---------------- bf16 helpers ----------------
__device__ __forceinline__ uint32_t pack_bf16(float a, float b) {
    __nv_bfloat162 p = __floats2bfloat162_rn(a, b);
    return *(uint32_t*)&p;
}
__device__ __forceinline__ void mma_bf16(float* c, const uint32_t* a, const uint32_t* b) {
    asm volatile(
        "mma.sync.aligned.m16n8k16.row.col.f32.bf16.bf16.f32 "
        "{%0,%1,%2,%3}, {%4,%5,%6,%7}, {%8,%9}, {%0,%1,%2,%3};\n"
        : "+f"(c[0]), "+f"(c[1]), "+f"(c[2]), "+f"(c[3])
        : "r"(a[0]), "r"(a[1]), "r"(a[2]), "r"(a[3]), "r"(b[0]), "r"(b[1]));
}

// ---------------- fused GIN layer kernel ----------------
// Per 128-row block: agg(gather) -> GEMM1(+BN+ReLU) -> GEMM2(+ReLU) -> gout.
// A resident in smem full-K as split bf16 kpairs (hi/lo). W loaded per 32-k chunk.
#define AST 68    // A row stride in uint32 kpairs (64 + 4 pad): bank (4g+tig) bijective
#define BST 136   // B row stride in uint32: bank (8*tig+g) bijective
#define SM_AH 0
#define SM_AL (128 * AST)
#define SM_BH (2 * 128 * AST)
#define SM_BL (2 * 128 * AST + 16 * BST)
#define SMEM_U32 (2 * 128 * AST + 2 * 16 * BST)

__global__ __launch_bounds__(256, 2) void layer_kernel(
    const float* __restrict__ F,
    const float* __restrict__ W1, const float* __restrict__ b1,
    const float* __restrict__ gamma, const float* __restrict__ beta,
    const float* __restrict__ mean, const float* __restrict__ var,
    const float* __restrict__ W2, const float* __restrict__ b2,
    float* __restrict__ OUT, int Kw1)
{
    extern __shared__ uint32_t sm[];
    uint32_t* Ah = sm + SM_AH;
    uint32_t* Al = sm + SM_AL;
    uint32_t* Bh = sm + SM_BH;
    uint32_t* Bl = sm + SM_BL;

    const int tid  = threadIdx.x;
    const int wid  = tid >> 5;
    const int lane = tid & 31;
    const int g    = lane >> 2;
    const int tig  = lane & 3;
    const int wm   = wid & 1;
    const int wn   = wid >> 1;
    const int row0 = blockIdx.x * 128;

    // ===== stage 1: aggregation -> split bf16 into Ah/Al =====
    // warp w handles rows w*16 .. w*16+15; lane owns dims 4*lane..4*lane+3
    for (int i = 0; i < 16; i++) {
        int r = wid * 16 + i;
        int gr = row0 + r;
        float4 acc4 = make_float4(0.f, 0.f, 0.f, 0.f);
        if (gr < N_NODES) {
            acc4 = *(const float4*)&F[gr * DIMH + lane * 4];
            int s = g_off[gr], e = g_off[gr + 1];
            for (int base = s; base < e; base += 32) {
                int cnt = min(32, e - base);
                int idx = (base + lane < e) ? g_srcs[base + lane] : 0;
                int j = 0;
                for (; j + 4 <= cnt; j += 4) {
                    int s0 = __shfl_sync(0xFFFFFFFFu, idx, j);
                    int s1 = __shfl_sync(0xFFFFFFFFu, idx, j + 1);
                    int s2 = __shfl_sync(0xFFFFFFFFu, idx, j + 2);
                    int s3 = __shfl_sync(0xFFFFFFFFu, idx, j + 3);
                    float4 v0 = *(const float4*)&F[s0 * DIMH + lane * 4];
                    float4 v1 = *(const float4*)&F[s1 * DIMH + lane * 4];
                    float4 v2 = *(const float4*)&F[s2 * DIMH + lane * 4];
                    float4 v3 = *(const float4*)&F[s3 * DIMH + lane * 4];
                    acc4.x += v0.x + v1.x + v2.x + v3.x;
                    acc4.y += v0.y + v1.y + v2.y + v3.y;
                    acc4.z += v0.z + v1.z + v2.z + v3.z;
                    acc4.w += v0.w + v1.w + v2.w + v3.w;
                }
                for (; j < cnt; j++) {
                    int s0 = __shfl_sync(0xFFFFFFFFu, idx, j);
                    float4 v = *(const float4*)&F[s0 * DIMH + lane * 4];
                    acc4.x += v.x; acc4.y += v.y; acc4.z += v.z; acc4.w += v.w;
                }
            }
        }
        float hx = __bfloat162float(__float2bfloat16_rn(acc4.x));
        float hy = __bfloat162float(__float2bfloat16_rn(acc4.y));
        float hz = __bfloat162float(__float2bfloat16_rn(acc4.z));
        float hw = __bfloat162float(__float2bfloat16_rn(acc4.w));
        uint2 hv = make_uint2(pack_bf16(hx, hy), pack_bf16(hz, hw));
        uint2 lv = make_uint2(pack_bf16(acc4.x - hx, acc4.y - hy),
                              pack_bf16(acc4.z - hz, acc4.w - hw));
        *(uint2*)&Ah[r * AST + 2 * lane] = hv;
        *(uint2*)&Al[r * AST + 2 * lane] = lv;
    }

    float acc[4][4][4];

    // ===== macro-free double GEMM =====
    #pragma unroll 1
    for (int pass = 0; pass < 2; pass++) {
        const float* W = (pass == 0) ? W1 : W2;
        const int Kw = (pass == 0) ? Kw1 : DIMH;

        #pragma unroll
        for (int mi = 0; mi < 4; mi++)
            #pragma unroll
            for (int ni = 0; ni < 4; ni++)
                #pragma unroll
                for (int r = 0; r < 4; r++) acc[mi][ni][r] = 0.0f;

        for (int c = 0; c < 4; c++) {           // 4 k-chunks of 32
            // sync: previous chunk's frag reads (or stage-1/repack writes) done
            __syncthreads();
            // ---- load W chunk 32x128 -> Bh/Bl (2 cells/thread, uint4 stores) ----
            #pragma unroll
            for (int l = 0; l < 2; l++) {
                int idx = tid + l * 256;
                int kp = idx >> 5;            // 0..15 kpair
                int c4 = (idx & 31) * 4;      // n col
                int gk0 = c * 32 + 2 * kp, gk1 = gk0 + 1;
                float4 v0 = make_float4(0.f, 0.f, 0.f, 0.f);
                float4 v1 = make_float4(0.f, 0.f, 0.f, 0.f);
                if (gk0 < Kw) v0 = *(const float4*)&W[gk0 * DIMH + c4];
                if (gk1 < Kw) v1 = *(const float4*)&W[gk1 * DIMH + c4];
                float h0x = __bfloat162float(__float2bfloat16_rn(v0.x));
                float h0y = __bfloat162float(__float2bfloat16_rn(v0.y));
                float h0z = __bfloat162float(__float2bfloat16_rn(v0.z));
                float h0w = __bfloat162float(__float2bfloat16_rn(v0.w));
                float h1x = __bfloat162float(__float2bfloat16_rn(v1.x));
                float h1y = __bfloat162float(__float2bfloat16_rn(v1.y));
                float h1z = __bfloat162float(__float2bfloat16_rn(v1.z));
                float h1w = __bfloat162float(__float2bfloat16_rn(v1.w));
                uint4 hv = make_uint4(pack_bf16(h0x, h1x), pack_bf16(h0y, h1y),
                                      pack_bf16(h0z, h1z), pack_bf16(h0w, h1w));
                uint4 lv = make_uint4(pack_bf16(v0.x - h0x, v1.x - h1x),
                                      pack_bf16(v0.y - h0y, v1.y - h1y),
                                      pack_bf16(v0.z - h0z, v1.z - h1z),
                                      pack_bf16(v0.w - h0w, v1.w - h1w));
                *(uint4*)&Bh[kp * BST + c4] = hv;
                *(uint4*)&Bl[kp * BST + c4] = lv;
            }
            __syncthreads();

            #pragma unroll
            for (int ks = 0; ks < 2; ks++) {
                const int kp0 = c * 16 + ks * 8;
                uint32_t a_hi[4][4], a_lo[4][4];
                #pragma unroll
                for (int mi = 0; mi < 4; mi++) {
                    int rm = wm * 64 + mi * 16;
                    a_hi[mi][0] = Ah[(rm + g    ) * AST + kp0 + tig    ];
                    a_hi[mi][1] = Ah[(rm + g + 8) * AST + kp0 + tig    ];
                    a_hi[mi][2] = Ah[(rm + g    ) * AST + kp0 + tig + 4];
                    a_hi[mi][3] = Ah[(rm + g + 8) * AST + kp0 + tig + 4];
                    a_lo[mi][0] = Al[(rm + g    ) * AST + kp0 + tig    ];
                    a_lo[mi][1] = Al[(rm + g + 8) * AST + kp0 + tig    ];
                    a_lo[mi][2] = Al[(rm + g    ) * AST + kp0 + tig + 4];
                    a_lo[mi][3] = Al[(rm + g + 8) * AST + kp0 + tig + 4];
                }
                const int kb = ks * 8;
                #pragma unroll
                for (int ni = 0; ni < 4; ni++) {
                    int cn = wn * 32 + ni * 8;
                    uint32_t bh[2], bl[2];
                    bh[0] = Bh[(kb + tig    ) * BST + cn + g];
                    bh[1] = Bh[(kb + tig + 4) * BST + cn + g];
                    bl[0] = Bl[(kb + tig    ) * BST + cn + g];
                    bl[1] = Bl[(kb + tig + 4) * BST + cn + g];
                    #pragma unroll
                    for (int mi = 0; mi < 4; mi++) {
                        mma_bf16(acc[mi][ni], a_hi[mi], bh);
                        mma_bf16(acc[mi][ni], a_hi[mi], bl);
                        mma_bf16(acc[mi][ni], a_lo[mi], bh);
                    }
                }
            }
        }

        // ---- epilogue ----
        float sc[4][2], sh[4][2];
        #pragma unroll
        for (int ni = 0; ni < 4; ni++) {
            #pragma unroll
            for (int j = 0; j < 2; j++) {
                int col = wn * 32 + ni * 8 + 2 * tig + j;
                if (pass == 0) {
                    float s = gamma[col] * rsqrtf(var[col] + BN_EPS);
                    sc[ni][j] = s;
                    sh[ni][j] = beta[col] - mean[col] * s + b1[col] * s;
                } else {
                    sc[ni][j] = 1.0f;
                    sh[ni][j] = b2[col];
                }
            }
        }

        if (pass == 0) {
            // repack h = relu(acc*sc+sh) into Ah/Al as GEMM2's A
            __syncthreads();   // all frag reads of old A complete
            #pragma unroll
            for (int mi = 0; mi < 4; mi++) {
                int r0 = wm * 64 + mi * 16 + g;
                int r1 = r0 + 8;
                #pragma unroll
                for (int ni = 0; ni < 4; ni++) {
                    int kp = (wn * 32 + ni * 8 + 2 * tig) >> 1;  // kpair index
                    float o00 = fmaxf(acc[mi][ni][0] * sc[ni][0] + sh[ni][0], 0.0f);
                    float o01 = fmaxf(acc[mi][ni][1] * sc[ni][1] + sh[ni][1], 0.0f);
                    float o10 = fmaxf(acc[mi][ni][2] * sc[ni][0] + sh[ni][0], 0.0f);
                    float o11 = fmaxf(acc[mi][ni][3] * sc[ni][1] + sh[ni][1], 0.0f);
                    float h00 = __bfloat162float(__float2bfloat16_rn(o00));
                    float h01 = __bfloat162float(__float2bfloat16_rn(o01));
                    float h10 = __bfloat162float(__float2bfloat16_rn(o10));
                    float h11 = __bfloat162float(__float2bfloat16_rn(o11));
                    Ah[r0 * AST + kp] = pack_bf16(h00, h01);
                    Al[r0 * AST + kp] = pack_bf16(o00 - h00, o01 - h01);
                    Ah[r1 * AST + kp] = pack_bf16(h10, h11);
                    Al[r1 * AST + kp] = pack_bf16(o10 - h10, o11 - h11);
                }
            }
            // gemm2's first chunk begins with __syncthreads() -> writes visible
        } else {
            #pragma unroll
            for (int mi = 0; mi < 4; mi++) {
                int r0 = row0 + wm * 64 + mi * 16 + g;
                int r1 = r0 + 8;
                #pragma unroll
                for (int ni = 0; ni < 4; ni++) {
                    int c0 = wn * 32 + ni * 8 + 2 * tig;
                    if (r0 < N_NODES) {
                        float2 o;
                        o.x = fmaxf(acc[mi][ni][0] * sc[ni][0] + sh[ni][0], 0.0f);
                        o.y = fmaxf(acc[mi][ni][1] * sc[ni][1] + sh[ni][1], 0.0f);
                        *(float2*)&OUT[r0 * DIMH + c0] = o;
                    }
                    if (r1 < N_NODES) {
                        float2 o;
                        o.x = fmaxf(acc[mi][ni][2] * sc[ni][0] + sh[ni][0], 0.0f);
                        o.y = fmaxf(acc[mi][ni][3] * sc[ni][1] + sh[ni][1], 0.0f);
                        *(float2*)&OUT[r1 * DIMH + c0] = o;
                    }
                }
            }
        }
    }
}

// ---------------- pooling ----------------
__global__ void pool_kernel(const int* __restrict__ batch, const float* __restrict__ h,
                            float* __restrict__ pool) {
    int i = blockIdx.x * blockDim.x + threadIdx.x;
    if (i < N_NODES * DIMH) {
        int n = i >> 7, d = i & 127;
        atomicAdd(&pool[batch[n] * DIMH + d], h[i]);
    }
}

// ---------------- head ----------------
__global__ void head_kernel(const float* __restrict__ pool,
                            const float* __restrict__ l1w, const float* __restrict__ l1b,
                            const float* __restrict__ l2w, const float* __restrict__ l2b,
                            float* __restrict__ out) {
    __shared__ float hg[DIMH];
    __shared__ float o1[LIN1_DIM];
    int gph = blockIdx.x;
    int t = threadIdx.x;  // 128
    hg[t] = pool[gph * DIMH + t];
    __syncthreads();
    if (t < LIN1_DIM) {
        float s = l1b[t];
        #pragma unroll 8
        for (int k = 0; k < DIMH; k++) s += hg[k] * l1w[k * LIN1_DIM + t];
        o1[t] = fmaxf(s, 0.0f);
    }
    __syncthreads();
    if (t == 0) {
        float s = l2b[0];
        #pragma unroll 8
        for (int j = 0; j < LIN1_DIM; j++) s += o1[j] * l2w[j];
        out[gph] = 1.0f / (1.0f + expf(-s));
    }
}

// ---------------- launch ----------------
extern "C" void kernel_launch(void* const* d_in, const int* in_sizes, int n_in,
                              void* d_out, int out_size) {
    const float* x          = (const float*)d_in[0];
    const int*   edge_index = (const int*)d_in[1];
    const int*   batch      = (const int*)d_in[2];
    const float* w[3][7];
    const float* b2[3];
    for (int l = 0; l < 3; l++) {
        int base = 3 + l * 8;
        w[l][0] = (const float*)d_in[base + 0];
        w[l][1] = (const float*)d_in[base + 1];
        w[l][2] = (const float*)d_in[base + 2];
        w[l][3] = (const float*)d_in[base + 3];
        w[l][4] = (const float*)d_in[base + 4];
        w[l][5] = (const float*)d_in[base + 5];
        w[l][6] = (const float*)d_in[base + 6];
        b2[l]   = (const float*)d_in[base + 7];
    }
    const float* l1w = (const float*)d_in[27];
    const float* l1b = (const float*)d_in[28];
    const float* l2w = (const float*)d_in[29];
    const float* l2b = (const float*)d_in[30];
    float* out = (float*)d_out;

    const int* e_src = edge_index;
    const int* e_dst = edge_index + N_EDGES;

    static float* p_feat = nullptr;
    static float* p_out  = nullptr;
    static int*   p_cnt  = nullptr;
    static float* p_pool = nullptr;
    if (!p_feat) {
        cudaGetSymbolAddress((void**)&p_feat, g_feat);
        cudaGetSymbolAddress((void**)&p_out,  g_out);
        cudaGetSymbolAddress((void**)&p_cnt,  g_cnt);
        cudaGetSymbolAddress((void**)&p_pool, g_pool);
        cudaFuncSetAttribute(layer_kernel,
                             cudaFuncAttributeMaxDynamicSharedMemorySize,
                             SMEM_U32 * 4);
    }

    // ---- CSR build ----
    zero_int_kernel<<<(N_NODES + 255) / 256, 256>>>(p_cnt, N_NODES);
    count_kernel<<<(N_EDGES + 255) / 256, 256>>>(e_dst);
    scan_kernel<<<1, 1024>>>(N_NODES);
    scatter_kernel<<<(N_EDGES + 255) / 256, 256>>>(e_src, e_dst);

    // ---- pad x ----
    pad_x_kernel<<<(N_NODES * DIMH + 255) / 256, 256>>>(x);

    const int GRID = (N_NODES + 127) / 128;
    const size_t SMEM = SMEM_U32 * 4;

    // ---- 3 fused GIN layers (ping-pong feat <-> out) ----
    float* cur = p_feat;
    float* nxt = p_out;
    for (int l = 0; l < 3; l++) {
        int Kw1 = (l == 0) ? IN_DIM : DIMH;
        layer_kernel<<<GRID, 256, SMEM>>>(cur,
                                          w[l][0], w[l][1], w[l][2], w[l][3],
                                          w[l][4], w[l][5], w[l][6], b2[l],
                                          nxt, Kw1);
        float* t = cur; cur = nxt; nxt = t;
    }

    // ---- pool + head ----
    zero_float_kernel<<<(N_GRAPHS * DIMH + 255) / 256, 256>>>(p_pool, N_GRAPHS * DIMH);
    pool_kernel<<<(N_NODES * DIMH + 255) / 256, 256>>>(batch, cur, p_pool);
    head_kernel<<<N_GRAPHS, 128>>>(p_pool, l1w, l1b, l2w, l2b, out);
}

// round 6
// speedup vs baseline: 1.0765x; 1.0765x over previous
#include <cuda_runtime.h>
#include <cuda_bf16.h>
#include <math.h>
#include <stdint.h>

#define N_NODES 50000
#define N_EDGES 800000
#define N_GRAPHS 512
#define IN_DIM 126
#define DIMH 128
#define LIN1_DIM 64
#define BN_EPS 1e-5f

// ---------------- device scratch ----------------
__device__ float g_feat[N_NODES * DIMH];
__device__ float g_a[N_NODES * DIMH];
__device__ float g_h[N_NODES * DIMH];
__device__ int   g_cnt[N_NODES];
__device__ int   g_off[N_NODES + 1];
__device__ int   g_cur[N_NODES];
__device__ int   g_srcs[N_EDGES];
__device__ float g_pool[N_GRAPHS * DIMH];

// ---------------- utility kernels ----------------
__global__ void count_kernel(const int* __restrict__ dst) {
    int i = blockIdx.x * blockDim.x + threadIdx.x;
    if (i < N_EDGES) atomicAdd(&g_cnt[dst[i]], 1);
}

// exclusive scan over g_cnt -> g_off and g_cur (single block)
__global__ void scan_kernel(int n) {
    __shared__ int warp_sums[32];
    __shared__ int s_carry;
    int tid = threadIdx.x;
    int lane = tid & 31, wid = tid >> 5;
    const int NW = 32;
    if (tid == 0) s_carry = 0;
    __syncthreads();
    for (int base = 0; base < n; base += blockDim.x) {
        int i = base + tid;
        int v = (i < n) ? g_cnt[i] : 0;
        int x = v;
        #pragma unroll
        for (int o = 1; o < 32; o <<= 1) {
            int t = __shfl_up_sync(0xFFFFFFFFu, x, o);
            if (lane >= o) x += t;
        }
        if (lane == 31) warp_sums[wid] = x;
        __syncthreads();
        if (wid == 0) {
            int s = (lane < NW) ? warp_sums[lane] : 0;
            #pragma unroll
            for (int o = 1; o < 32; o <<= 1) {
                int t = __shfl_up_sync(0xFFFFFFFFu, s, o);
                if (lane >= o) s += t;
            }
            warp_sums[lane] = s;
        }
        __syncthreads();
        int excl = s_carry + x - v + (wid > 0 ? warp_sums[wid - 1] : 0);
        if (i < n) { g_off[i] = excl; g_cur[i] = excl; }
        __syncthreads();
        if (tid == 0) s_carry += warp_sums[NW - 1];
        __syncthreads();
    }
    if (threadIdx.x == 0) g_off[n] = s_carry;
}

__global__ void scatter_kernel(const int* __restrict__ src, const int* __restrict__ dst) {
    int i = blockIdx.x * blockDim.x + threadIdx.x;
    if (i < N_EDGES) {
        int p = atomicAdd(&g_cur[dst[i]], 1);
        g_srcs[p] = src[i];
    }
}

__global__ void pad_x_kernel(const float* __restrict__ x) {
    int i = blockIdx.x * blockDim.x + threadIdx.x;
    if (i < N_NODES * DIMH) {
        int n = i >> 7, d = i & 127;
        g_feat[i] = (d < IN_DIM) ? x[n * IN_DIM + d] : 0.0f;
    }
}

// ---------------- aggregation: warp per node, float4 lanes, MLP 8 ----------
__global__ __launch_bounds__(256) void agg_kernel(const float* __restrict__ F,
                                                  float* __restrict__ out) {
    int warp = (blockIdx.x * blockDim.x + threadIdx.x) >> 5;
    int lane = threadIdx.x & 31;
    if (warp >= N_NODES) return;
    int s = g_off[warp], e = g_off[warp + 1];
    float4 acc = *(const float4*)&F[warp * DIMH + lane * 4];
    for (int base = s; base < e; base += 32) {
        int cnt = min(32, e - base);
        int idx = (base + lane < e) ? g_srcs[base + lane] : 0;
        int j = 0;
        for (; j + 8 <= cnt; j += 8) {
            int t0 = __shfl_sync(0xFFFFFFFFu, idx, j);
            int t1 = __shfl_sync(0xFFFFFFFFu, idx, j + 1);
            int t2 = __shfl_sync(0xFFFFFFFFu, idx, j + 2);
            int t3 = __shfl_sync(0xFFFFFFFFu, idx, j + 3);
            int t4 = __shfl_sync(0xFFFFFFFFu, idx, j + 4);
            int t5 = __shfl_sync(0xFFFFFFFFu, idx, j + 5);
            int t6 = __shfl_sync(0xFFFFFFFFu, idx, j + 6);
            int t7 = __shfl_sync(0xFFFFFFFFu, idx, j + 7);
            float4 v0 = *(const float4*)&F[t0 * DIMH + lane * 4];
            float4 v1 = *(const float4*)&F[t1 * DIMH + lane * 4];
            float4 v2 = *(const float4*)&F[t2 * DIMH + lane * 4];
            float4 v3 = *(const float4*)&F[t3 * DIMH + lane * 4];
            float4 v4 = *(const float4*)&F[t4 * DIMH + lane * 4];
            float4 v5 = *(const float4*)&F[t5 * DIMH + lane * 4];
            float4 v6 = *(const float4*)&F[t6 * DIMH + lane * 4];
            float4 v7 = *(const float4*)&F[t7 * DIMH + lane * 4];
            acc.x += ((v0.x + v1.x) + (v2.x + v3.x)) + ((v4.x + v5.x) + (v6.x + v7.x));
            acc.y += ((v0.y + v1.y) + (v2.y + v3.y)) + ((v4.y + v5.y) + (v6.y + v7.y));
            acc.z += ((v0.z + v1.z) + (v2.z + v3.z)) + ((v4.z + v5.z) + (v6.z + v7.z));
            acc.w += ((v0.w + v1.w) + (v2.w + v3.w)) + ((v4.w + v5.w) + (v6.w + v7.w));
        }
        for (; j < cnt; j++) {
            int t0 = __shfl_sync(0xFFFFFFFFu, idx, j);
            float4 v = *(const float4*)&F[t0 * DIMH + lane * 4];
            acc.x += v.x; acc.y += v.y; acc.z += v.z; acc.w += v.w;
        }
    }
    *(float4*)&out[warp * DIMH + lane * 4] = acc;
}

// ---------------- bf16 split tensor-core GEMM (A-prefetch pipelined) -------
__device__ __forceinline__ uint32_t pack_bf16(float a, float b) {
    __nv_bfloat162 p = __floats2bfloat162_rn(a, b);
    return *(uint32_t*)&p;
}
__device__ __forceinline__ void mma_bf16(float* c, const uint32_t* a, const uint32_t* b) {
    asm volatile(
        "mma.sync.aligned.m16n8k16.row.col.f32.bf16.bf16.f32 "
        "{%0,%1,%2,%3}, {%4,%5,%6,%7}, {%8,%9}, {%0,%1,%2,%3};\n"
        : "+f"(c[0]), "+f"(c[1]), "+f"(c[2]), "+f"(c[3])
        : "r"(a[0]), "r"(a[1]), "r"(a[2]), "r"(a[3]), "r"(b[0]), "r"(b[1]));
}

#define AST 20    // A row stride in uint32 kpairs
#define BST 136   // B row stride in uint32
__global__ __launch_bounds__(256, 2) void gemm_tc_kernel(
    const float* __restrict__ A, const float* __restrict__ W,
    const float* __restrict__ bias,
    const float* __restrict__ gamma, const float* __restrict__ beta,
    const float* __restrict__ mean, const float* __restrict__ var,
    float* __restrict__ C, int M, int Kw, int mode)
{
    __shared__ uint32_t Ah[128][AST];
    __shared__ uint32_t Al[128][AST];
    __shared__ uint32_t Bh[16][BST];
    __shared__ uint32_t Bl[16][BST];

    const int tid  = threadIdx.x;
    const int wid  = tid >> 5;
    const int lane = tid & 31;
    const int g    = lane >> 2;
    const int tig  = lane & 3;
    const int wm   = wid & 1;
    const int wn   = wid >> 1;
    const int row0 = blockIdx.x * 128;

    float acc[4][4][4];
    #pragma unroll
    for (int mi = 0; mi < 4; mi++)
        #pragma unroll
        for (int ni = 0; ni < 4; ni++)
            #pragma unroll
            for (int r = 0; r < 4; r++) acc[mi][ni][r] = 0.0f;

    // A-load geometry fixed per thread; only k-chunk base changes
    int arow[4], acol[4];
    #pragma unroll
    for (int l = 0; l < 4; l++) {
        int idx = tid + l * 256;
        arow[l] = idx >> 3;
        acol[l] = (idx & 7) * 4;
    }

    // preload chunk 0
    float4 av[4];
    #pragma unroll
    for (int l = 0; l < 4; l++) {
        int gr = row0 + arow[l];
        av[l] = (gr < M) ? *(const float4*)&A[gr * DIMH + acol[l]]
                         : make_float4(0.f, 0.f, 0.f, 0.f);
    }

    for (int c = 0; c < 4; c++) {
        // ---- store staged A regs -> smem (split bf16) ----
        #pragma unroll
        for (int l = 0; l < 4; l++) {
            float4 v = av[l];
            float hx = __bfloat162float(__float2bfloat16_rn(v.x));
            float hy = __bfloat162float(__float2bfloat16_rn(v.y));
            float hz = __bfloat162float(__float2bfloat16_rn(v.z));
            float hw = __bfloat162float(__float2bfloat16_rn(v.w));
            int r = arow[l], c2 = acol[l] >> 1;
            Ah[r][c2]     = pack_bf16(hx, hy);
            Ah[r][c2 + 1] = pack_bf16(hz, hw);
            Al[r][c2]     = pack_bf16(v.x - hx, v.y - hy);
            Al[r][c2 + 1] = pack_bf16(v.z - hz, v.w - hw);
        }
        // ---- W chunk 32x128 -> Bh/Bl ----
        #pragma unroll
        for (int l = 0; l < 2; l++) {
            int idx = tid + l * 256;
            int kp = idx >> 5;
            int c4 = (idx & 31) * 4;
            int gk0 = c * 32 + 2 * kp, gk1 = gk0 + 1;
            float4 v0 = make_float4(0.f, 0.f, 0.f, 0.f);
            float4 v1 = make_float4(0.f, 0.f, 0.f, 0.f);
            if (gk0 < Kw) v0 = *(const float4*)&W[gk0 * DIMH + c4];
            if (gk1 < Kw) v1 = *(const float4*)&W[gk1 * DIMH + c4];
            float h0x = __bfloat162float(__float2bfloat16_rn(v0.x));
            float h0y = __bfloat162float(__float2bfloat16_rn(v0.y));
            float h0z = __bfloat162float(__float2bfloat16_rn(v0.z));
            float h0w = __bfloat162float(__float2bfloat16_rn(v0.w));
            float h1x = __bfloat162float(__float2bfloat16_rn(v1.x));
            float h1y = __bfloat162float(__float2bfloat16_rn(v1.y));
            float h1z = __bfloat162float(__float2bfloat16_rn(v1.z));
            float h1w = __bfloat162float(__float2bfloat16_rn(v1.w));
            Bh[kp][c4]     = pack_bf16(h0x, h1x);
            Bh[kp][c4 + 1] = pack_bf16(h0y, h1y);
            Bh[kp][c4 + 2] = pack_bf16(h0z, h1z);
            Bh[kp][c4 + 3] = pack_bf16(h0w, h1w);
            Bl[kp][c4]     = pack_bf16(v0.x - h0x, v1.x - h1x);
            Bl[kp][c4 + 1] = pack_bf16(v0.y - h0y, v1.y - h1y);
            Bl[kp][c4 + 2] = pack_bf16(v0.z - h0z, v1.z - h1z);
            Bl[kp][c4 + 3] = pack_bf16(v0.w - h0w, v1.w - h1w);
        }
        __syncthreads();

        // ---- prefetch next A chunk while mma runs ----
        if (c < 3) {
            int k0 = (c + 1) * 32;
            #pragma unroll
            for (int l = 0; l < 4; l++) {
                int gr = row0 + arow[l];
                av[l] = (gr < M) ? *(const float4*)&A[gr * DIMH + k0 + acol[l]]
                                 : make_float4(0.f, 0.f, 0.f, 0.f);
            }
        }

        #pragma unroll
        for (int ks = 0; ks < 2; ks++) {
            const int kk2 = ks * 8;
            uint32_t a_hi[4][4], a_lo[4][4];
            #pragma unroll
            for (int mi = 0; mi < 4; mi++) {
                int rm = wm * 64 + mi * 16;
                a_hi[mi][0] = Ah[rm + g    ][kk2 + tig    ];
                a_hi[mi][1] = Ah[rm + g + 8][kk2 + tig    ];
                a_hi[mi][2] = Ah[rm + g    ][kk2 + tig + 4];
                a_hi[mi][3] = Ah[rm + g + 8][kk2 + tig + 4];
                a_lo[mi][0] = Al[rm + g    ][kk2 + tig    ];
                a_lo[mi][1] = Al[rm + g + 8][kk2 + tig    ];
                a_lo[mi][2] = Al[rm + g    ][kk2 + tig + 4];
                a_lo[mi][3] = Al[rm + g + 8][kk2 + tig + 4];
            }
            #pragma unroll
            for (int ni = 0; ni < 4; ni++) {
                int cn = wn * 32 + ni * 8;
                uint32_t bh[2], bl[2];
                bh[0] = Bh[kk2 + tig    ][cn + g];
                bh[1] = Bh[kk2 + tig + 4][cn + g];
                bl[0] = Bl[kk2 + tig    ][cn + g];
                bl[1] = Bl[kk2 + tig + 4][cn + g];
                #pragma unroll
                for (int mi = 0; mi < 4; mi++) {
                    mma_bf16(acc[mi][ni], a_hi[mi], bh);
                    mma_bf16(acc[mi][ni], a_hi[mi], bl);
                    mma_bf16(acc[mi][ni], a_lo[mi], bh);
                }
            }
        }
        __syncthreads();
    }

    // ---- epilogue ----
    float sc[4][2], sh[4][2];
    #pragma unroll
    for (int ni = 0; ni < 4; ni++) {
        #pragma unroll
        for (int j = 0; j < 2; j++) {
            int col = wn * 32 + ni * 8 + 2 * tig + j;
            float b = bias[col];
            if (mode == 0) {
                float s = gamma[col] * rsqrtf(var[col] + BN_EPS);
                sc[ni][j] = s;
                sh[ni][j] = beta[col] - mean[col] * s + b * s;
            } else {
                sc[ni][j] = 1.0f;
                sh[ni][j] = b;
            }
        }
    }
    #pragma unroll
    for (int mi = 0; mi < 4; mi++) {
        int r0 = row0 + wm * 64 + mi * 16 + g;
        int r1 = r0 + 8;
        #pragma unroll
        for (int ni = 0; ni < 4; ni++) {
            int c0 = wn * 32 + ni * 8 + 2 * tig;
            if (r0 < M) {
                float2 o;
                o.x = fmaxf(acc[mi][ni][0] * sc[ni][0] + sh[ni][0], 0.0f);
                o.y = fmaxf(acc[mi][ni][1] * sc[ni][1] + sh[ni][1], 0.0f);
                *(float2*)&C[r0 * DIMH + c0] = o;
            }
            if (r1 < M) {
                float2 o;
                o.x = fmaxf(acc[mi][ni][2] * sc[ni][0] + sh[ni][0], 0.0f);
                o.y = fmaxf(acc[mi][ni][3] * sc[ni][1] + sh[ni][1], 0.0f);
                *(float2*)&C[r1 * DIMH + c0] = o;
            }
        }
    }
}

// ---------------- pooling ----------------
__global__ void pool_kernel(const int* __restrict__ batch, const float* __restrict__ h,
                            float* __restrict__ pool) {
    int i = blockIdx.x * blockDim.x + threadIdx.x;
    if (i < N_NODES * DIMH) {
        int n = i >> 7, d = i & 127;
        atomicAdd(&pool[batch[n] * DIMH + d], h[i]);
    }
}

// ---------------- head ----------------
__global__ void head_kernel(const float* __restrict__ pool,
                            const float* __restrict__ l1w, const float* __restrict__ l1b,
                            const float* __restrict__ l2w, const float* __restrict__ l2b,
                            float* __restrict__ out) {
    __shared__ float hg[DIMH];
    __shared__ float o1[LIN1_DIM];
    int gph = blockIdx.x;
    int t = threadIdx.x;  // 128
    hg[t] = pool[gph * DIMH + t];
    __syncthreads();
    if (t < LIN1_DIM) {
        float s = l1b[t];
        #pragma unroll 8
        for (int k = 0; k < DIMH; k++) s += hg[k] * l1w[k * LIN1_DIM + t];
        o1[t] = fmaxf(s, 0.0f);
    }
    __syncthreads();
    if (t == 0) {
        float s = l2b[0];
        #pragma unroll 8
        for (int j = 0; j < LIN1_DIM; j++) s += o1[j] * l2w[j];
        out[gph] = 1.0f / (1.0f + expf(-s));
    }
}

// ---------------- launch ----------------
extern "C" void kernel_launch(void* const* d_in, const int* in_sizes, int n_in,
                              void* d_out, int out_size) {
    const float* x          = (const float*)d_in[0];
    const int*   edge_index = (const int*)d_in[1];
    const int*   batch      = (const int*)d_in[2];
    const float* w[3][7];
    const float* b2[3];
    for (int l = 0; l < 3; l++) {
        int base = 3 + l * 8;
        w[l][0] = (const float*)d_in[base + 0];
        w[l][1] = (const float*)d_in[base + 1];
        w[l][2] = (const float*)d_in[base + 2];
        w[l][3] = (const float*)d_in[base + 3];
        w[l][4] = (const float*)d_in[base + 4];
        w[l][5] = (const float*)d_in[base + 5];
        w[l][6] = (const float*)d_in[base + 6];
        b2[l]   = (const float*)d_in[base + 7];
    }
    const float* l1w = (const float*)d_in[27];
    const float* l1b = (const float*)d_in[28];
    const float* l2w = (const float*)d_in[29];
    const float* l2b = (const float*)d_in[30];
    float* out = (float*)d_out;

    const int* e_src = edge_index;
    const int* e_dst = edge_index + N_EDGES;

    static float* p_feat = nullptr;
    static float* p_a    = nullptr;
    static float* p_h    = nullptr;
    static int*   p_cnt  = nullptr;
    static float* p_pool = nullptr;
    if (!p_feat) {
        cudaGetSymbolAddress((void**)&p_feat, g_feat);
        cudaGetSymbolAddress((void**)&p_a,    g_a);
        cudaGetSymbolAddress((void**)&p_h,    g_h);
        cudaGetSymbolAddress((void**)&p_cnt,  g_cnt);
        cudaGetSymbolAddress((void**)&p_pool, g_pool);
    }

    // ---- CSR build (zeroing via capture-safe memset nodes) ----
    cudaMemsetAsync(p_cnt, 0, N_NODES * sizeof(int));
    count_kernel<<<(N_EDGES + 255) / 256, 256>>>(e_dst);
    scan_kernel<<<1, 1024>>>(N_NODES);
    scatter_kernel<<<(N_EDGES + 255) / 256, 256>>>(e_src, e_dst);

    // ---- pad x ----
    pad_x_kernel<<<(N_NODES * DIMH + 255) / 256, 256>>>(x);

    const int GEMM_GRID = (N_NODES + 127) / 128;
    const int AGG_GRID  = (N_NODES * 32 + 255) / 256;

    // ---- 3 GIN layers ----
    for (int l = 0; l < 3; l++) {
        int Kw = (l == 0) ? IN_DIM : DIMH;
        agg_kernel<<<AGG_GRID, 256>>>(p_feat, p_a);
        gemm_tc_kernel<<<GEMM_GRID, 256>>>(p_a, w[l][0], w[l][1],
                                           w[l][2], w[l][3], w[l][4], w[l][5],
                                           p_h, N_NODES, Kw, /*mode=*/0);
        gemm_tc_kernel<<<GEMM_GRID, 256>>>(p_h, w[l][6], b2[l],
                                           nullptr, nullptr, nullptr, nullptr,
                                           p_feat, N_NODES, DIMH, /*mode=*/1);
    }

    // ---- pool + head ----
    cudaMemsetAsync(p_pool, 0, N_GRAPHS * DIMH * sizeof(float));
    pool_kernel<<<(N_NODES * DIMH + 255) / 256, 256>>>(batch, p_feat, p_pool);
    head_kernel<<<N_GRAPHS, 128>>>(p_pool, l1w, l1b, l2w, l2b, out);
}

// round 7
// speedup vs baseline: 1.3535x; 1.2573x over previous
#include <cuda_runtime.h>
#include <cuda_bf16.h>
#include <math.h>
#include <stdint.h>

#define N_NODES 50000
#define N_EDGES 800000
#define N_GRAPHS 512
#define IN_DIM 126
#define DIMH 128
#define LIN1_DIM 64
#define BN_EPS 1e-5f

// ---------------- device scratch ----------------
__device__ float g_feat[N_NODES * DIMH];
__device__ float g_a[N_NODES * DIMH];
__device__ int   g_cnt[N_NODES];
__device__ int   g_off[N_NODES + 1];
__device__ int   g_cur[N_NODES];
__device__ int   g_srcs[N_EDGES];
__device__ float g_pool[N_GRAPHS * DIMH];

// ---------------- utility kernels ----------------
__global__ void count_kernel(const int* __restrict__ dst) {
    int i = blockIdx.x * blockDim.x + threadIdx.x;
    if (i < N_EDGES) atomicAdd(&g_cnt[dst[i]], 1);
}

__global__ void scan_kernel(int n) {
    __shared__ int warp_sums[32];
    __shared__ int s_carry;
    int tid = threadIdx.x;
    int lane = tid & 31, wid = tid >> 5;
    const int NW = 32;
    if (tid == 0) s_carry = 0;
    __syncthreads();
    for (int base = 0; base < n; base += blockDim.x) {
        int i = base + tid;
        int v = (i < n) ? g_cnt[i] : 0;
        int x = v;
        #pragma unroll
        for (int o = 1; o < 32; o <<= 1) {
            int t = __shfl_up_sync(0xFFFFFFFFu, x, o);
            if (lane >= o) x += t;
        }
        if (lane == 31) warp_sums[wid] = x;
        __syncthreads();
        if (wid == 0) {
            int s = (lane < NW) ? warp_sums[lane] : 0;
            #pragma unroll
            for (int o = 1; o < 32; o <<= 1) {
                int t = __shfl_up_sync(0xFFFFFFFFu, s, o);
                if (lane >= o) s += t;
            }
            warp_sums[lane] = s;
        }
        __syncthreads();
        int excl = s_carry + x - v + (wid > 0 ? warp_sums[wid - 1] : 0);
        if (i < n) { g_off[i] = excl; g_cur[i] = excl; }
        __syncthreads();
        if (tid == 0) s_carry += warp_sums[NW - 1];
        __syncthreads();
    }
    if (threadIdx.x == 0) g_off[n] = s_carry;
}

__global__ void scatter_kernel(const int* __restrict__ src, const int* __restrict__ dst) {
    int i = blockIdx.x * blockDim.x + threadIdx.x;
    if (i < N_EDGES) {
        int p = atomicAdd(&g_cur[dst[i]], 1);
        g_srcs[p] = src[i];
    }
}

// pad x [N,126] -> g_feat [N,128] using float2 (rows are 8B-aligned: 126*4=504)
__global__ void pad_x_kernel(const float* __restrict__ x) {
    int i = blockIdx.x * blockDim.x + threadIdx.x;
    if (i < N_NODES * 64) {
        int n = i >> 6, p = i & 63;
        float2 v = make_float2(0.f, 0.f);
        if (p < 63) v = *(const float2*)&x[n * IN_DIM + 2 * p];
        *(float2*)&g_feat[n * DIMH + 2 * p] = v;
    }
}

// ---------------- aggregation: warp per node, float4 lanes (R4-proven) -----
__global__ __launch_bounds__(256) void agg_kernel(const float* __restrict__ F,
                                                  float* __restrict__ out) {
    int warp = (blockIdx.x * blockDim.x + threadIdx.x) >> 5;
    int lane = threadIdx.x & 31;
    if (warp >= N_NODES) return;
    int s = g_off[warp], e = g_off[warp + 1];
    float4 acc = *(const float4*)&F[warp * DIMH + lane * 4];
    for (int base = s; base < e; base += 32) {
        int cnt = min(32, e - base);
        int idx = (base + lane < e) ? g_srcs[base + lane] : 0;
        int j = 0;
        for (; j + 4 <= cnt; j += 4) {
            int s0 = __shfl_sync(0xFFFFFFFFu, idx, j);
            int s1 = __shfl_sync(0xFFFFFFFFu, idx, j + 1);
            int s2 = __shfl_sync(0xFFFFFFFFu, idx, j + 2);
            int s3 = __shfl_sync(0xFFFFFFFFu, idx, j + 3);
            float4 v0 = *(const float4*)&F[s0 * DIMH + lane * 4];
            float4 v1 = *(const float4*)&F[s1 * DIMH + lane * 4];
            float4 v2 = *(const float4*)&F[s2 * DIMH + lane * 4];
            float4 v3 = *(const float4*)&F[s3 * DIMH + lane * 4];
            acc.x += v0.x + v1.x + v2.x + v3.x;
            acc.y += v0.y + v1.y + v2.y + v3.y;
            acc.z += v0.z + v1.z + v2.z + v3.z;
            acc.w += v0.w + v1.w + v2.w + v3.w;
        }
        for (; j < cnt; j++) {
            int s0 = __shfl_sync(0xFFFFFFFFu, idx, j);
            float4 v = *(const float4*)&F[s0 * DIMH + lane * 4];
            acc.x += v.x; acc.y += v.y; acc.z += v.z; acc.w += v.w;
        }
    }
    *(float4*)&out[warp * DIMH + lane * 4] = acc;
}

// ---------------- bf16 helpers ----------------
__device__ __forceinline__ uint32_t pack_bf16(float a, float b) {
    __nv_bfloat162 p = __floats2bfloat162_rn(a, b);
    return *(uint32_t*)&p;
}
__device__ __forceinline__ void mma_bf16(float* c, const uint32_t* a, const uint32_t* b) {
    asm volatile(
        "mma.sync.aligned.m16n8k16.row.col.f32.bf16.bf16.f32 "
        "{%0,%1,%2,%3}, {%4,%5,%6,%7}, {%8,%9}, {%0,%1,%2,%3};\n"
        : "+f"(c[0]), "+f"(c[1]), "+f"(c[2]), "+f"(c[3])
        : "r"(a[0]), "r"(a[1]), "r"(a[2]), "r"(a[3]), "r"(b[0]), "r"(b[1]));
}

// ---------------- fused double-GEMM per GIN layer ----------------
// in: g_a (after agg). GEMM1(+BN+ReLU) -> h in smem -> GEMM2(+ReLU) -> OUT.
#define AST 20    // streamed A chunk stride (u32 kpairs)
#define BST 136   // B stride (u32)
#define HST 68    // resident H stride (u32 kpairs): bank (4g+tig) bijective
// smem layout (u32 offsets)
#define SM_AH 0
#define SM_AL (128 * AST)
#define SM_BH (2 * 128 * AST)
#define SM_BL (SM_BH + 16 * BST)
#define SM_HH (SM_BH + 2 * 16 * BST)
#define SM_HL (SM_HH + 128 * HST)
#define SMEM_U32 (SM_HH + 2 * 128 * HST)

__global__ __launch_bounds__(256, 2) void layer_gemm_kernel(
    const float* __restrict__ A,
    const float* __restrict__ W1, const float* __restrict__ b1,
    const float* __restrict__ gamma, const float* __restrict__ beta,
    const float* __restrict__ mean, const float* __restrict__ var,
    const float* __restrict__ W2, const float* __restrict__ b2,
    float* __restrict__ OUT, int Kw1)
{
    extern __shared__ uint32_t sm[];
    uint32_t* Ah = sm + SM_AH;
    uint32_t* Al = sm + SM_AL;
    uint32_t* Bh = sm + SM_BH;
    uint32_t* Bl = sm + SM_BL;
    uint32_t* Hh = sm + SM_HH;
    uint32_t* Hl = sm + SM_HL;

    const int tid  = threadIdx.x;
    const int wid  = tid >> 5;
    const int lane = tid & 31;
    const int g    = lane >> 2;
    const int tig  = lane & 3;
    const int wm   = wid & 1;
    const int wn   = wid >> 1;
    const int row0 = blockIdx.x * 128;

    float acc[4][4][4];

    // =========== GEMM1: A(global, streamed) x W1 ===========
    #pragma unroll
    for (int mi = 0; mi < 4; mi++)
        #pragma unroll
        for (int ni = 0; ni < 4; ni++)
            #pragma unroll
            for (int r = 0; r < 4; r++) acc[mi][ni][r] = 0.0f;

    for (int c = 0; c < 4; c++) {
        // ---- A chunk 128x32 -> Ah/Al ----
        #pragma unroll
        for (int l = 0; l < 4; l++) {
            int idx = tid + l * 256;
            int r = idx >> 3, c4 = (idx & 7) * 4;
            int gr = row0 + r;
            float4 v = make_float4(0.f, 0.f, 0.f, 0.f);
            if (gr < N_NODES) v = *(const float4*)&A[gr * DIMH + c * 32 + c4];
            float hx = __bfloat162float(__float2bfloat16_rn(v.x));
            float hy = __bfloat162float(__float2bfloat16_rn(v.y));
            float hz = __bfloat162float(__float2bfloat16_rn(v.z));
            float hw = __bfloat162float(__float2bfloat16_rn(v.w));
            int c2 = c4 >> 1;
            Ah[r * AST + c2]     = pack_bf16(hx, hy);
            Ah[r * AST + c2 + 1] = pack_bf16(hz, hw);
            Al[r * AST + c2]     = pack_bf16(v.x - hx, v.y - hy);
            Al[r * AST + c2 + 1] = pack_bf16(v.z - hz, v.w - hw);
        }
        // ---- W1 chunk 32x128 -> Bh/Bl ----
        #pragma unroll
        for (int l = 0; l < 2; l++) {
            int idx = tid + l * 256;
            int kp = idx >> 5;
            int c4 = (idx & 31) * 4;
            int gk0 = c * 32 + 2 * kp, gk1 = gk0 + 1;
            float4 v0 = make_float4(0.f, 0.f, 0.f, 0.f);
            float4 v1 = make_float4(0.f, 0.f, 0.f, 0.f);
            if (gk0 < Kw1) v0 = *(const float4*)&W1[gk0 * DIMH + c4];
            if (gk1 < Kw1) v1 = *(const float4*)&W1[gk1 * DIMH + c4];
            float h0x = __bfloat162float(__float2bfloat16_rn(v0.x));
            float h0y = __bfloat162float(__float2bfloat16_rn(v0.y));
            float h0z = __bfloat162float(__float2bfloat16_rn(v0.z));
            float h0w = __bfloat162float(__float2bfloat16_rn(v0.w));
            float h1x = __bfloat162float(__float2bfloat16_rn(v1.x));
            float h1y = __bfloat162float(__float2bfloat16_rn(v1.y));
            float h1z = __bfloat162float(__float2bfloat16_rn(v1.z));
            float h1w = __bfloat162float(__float2bfloat16_rn(v1.w));
            Bh[kp * BST + c4]     = pack_bf16(h0x, h1x);
            Bh[kp * BST + c4 + 1] = pack_bf16(h0y, h1y);
            Bh[kp * BST + c4 + 2] = pack_bf16(h0z, h1z);
            Bh[kp * BST + c4 + 3] = pack_bf16(h0w, h1w);
            Bl[kp * BST + c4]     = pack_bf16(v0.x - h0x, v1.x - h1x);
            Bl[kp * BST + c4 + 1] = pack_bf16(v0.y - h0y, v1.y - h1y);
            Bl[kp * BST + c4 + 2] = pack_bf16(v0.z - h0z, v1.z - h1z);
            Bl[kp * BST + c4 + 3] = pack_bf16(v0.w - h0w, v1.w - h1w);
        }
        __syncthreads();

        #pragma unroll
        for (int ks = 0; ks < 2; ks++) {
            const int kk2 = ks * 8;
            uint32_t a_hi[4][4], a_lo[4][4];
            #pragma unroll
            for (int mi = 0; mi < 4; mi++) {
                int rm = wm * 64 + mi * 16;
                a_hi[mi][0] = Ah[(rm + g    ) * AST + kk2 + tig    ];
                a_hi[mi][1] = Ah[(rm + g + 8) * AST + kk2 + tig    ];
                a_hi[mi][2] = Ah[(rm + g    ) * AST + kk2 + tig + 4];
                a_hi[mi][3] = Ah[(rm + g + 8) * AST + kk2 + tig + 4];
                a_lo[mi][0] = Al[(rm + g    ) * AST + kk2 + tig    ];
                a_lo[mi][1] = Al[(rm + g + 8) * AST + kk2 + tig    ];
                a_lo[mi][2] = Al[(rm + g    ) * AST + kk2 + tig + 4];
                a_lo[mi][3] = Al[(rm + g + 8) * AST + kk2 + tig + 4];
            }
            #pragma unroll
            for (int ni = 0; ni < 4; ni++) {
                int cn = wn * 32 + ni * 8;
                uint32_t bh[2], bl[2];
                bh[0] = Bh[(kk2 + tig    ) * BST + cn + g];
                bh[1] = Bh[(kk2 + tig + 4) * BST + cn + g];
                bl[0] = Bl[(kk2 + tig    ) * BST + cn + g];
                bl[1] = Bl[(kk2 + tig + 4) * BST + cn + g];
                #pragma unroll
                for (int mi = 0; mi < 4; mi++) {
                    mma_bf16(acc[mi][ni], a_hi[mi], bh);
                    mma_bf16(acc[mi][ni], a_hi[mi], bl);
                    mma_bf16(acc[mi][ni], a_lo[mi], bh);
                }
            }
        }
        __syncthreads();
    }

    // ---- epilogue1: BN+ReLU, repack h -> Hh/Hl ----
    {
        float sc[4][2], sh[4][2];
        #pragma unroll
        for (int ni = 0; ni < 4; ni++) {
            #pragma unroll
            for (int j = 0; j < 2; j++) {
                int col = wn * 32 + ni * 8 + 2 * tig + j;
                float s = gamma[col] * rsqrtf(var[col] + BN_EPS);
                sc[ni][j] = s;
                sh[ni][j] = beta[col] - mean[col] * s + b1[col] * s;
            }
        }
        #pragma unroll
        for (int mi = 0; mi < 4; mi++) {
            int r0 = wm * 64 + mi * 16 + g;
            int r1 = r0 + 8;
            #pragma unroll
            for (int ni = 0; ni < 4; ni++) {
                int kp = wn * 16 + ni * 4 + tig;
                float o00 = fmaxf(acc[mi][ni][0] * sc[ni][0] + sh[ni][0], 0.0f);
                float o01 = fmaxf(acc[mi][ni][1] * sc[ni][1] + sh[ni][1], 0.0f);
                float o10 = fmaxf(acc[mi][ni][2] * sc[ni][0] + sh[ni][0], 0.0f);
                float o11 = fmaxf(acc[mi][ni][3] * sc[ni][1] + sh[ni][1], 0.0f);
                float h00 = __bfloat162float(__float2bfloat16_rn(o00));
                float h01 = __bfloat162float(__float2bfloat16_rn(o01));
                float h10 = __bfloat162float(__float2bfloat16_rn(o10));
                float h11 = __bfloat162float(__float2bfloat16_rn(o11));
                Hh[r0 * HST + kp] = pack_bf16(h00, h01);
                Hl[r0 * HST + kp] = pack_bf16(o00 - h00, o01 - h01);
                Hh[r1 * HST + kp] = pack_bf16(h10, h11);
                Hl[r1 * HST + kp] = pack_bf16(o10 - h10, o11 - h11);
            }
        }
    }

    // =========== GEMM2: H(smem) x W2 ===========
    #pragma unroll
    for (int mi = 0; mi < 4; mi++)
        #pragma unroll
        for (int ni = 0; ni < 4; ni++)
            #pragma unroll
            for (int r = 0; r < 4; r++) acc[mi][ni][r] = 0.0f;

    for (int c = 0; c < 4; c++) {
        __syncthreads();   // B readers done (GEMM1 last chunk / prev chunk); H writes visible (c==0)
        // ---- W2 chunk 32x128 -> Bh/Bl ----
        #pragma unroll
        for (int l = 0; l < 2; l++) {
            int idx = tid + l * 256;
            int kp = idx >> 5;
            int c4 = (idx & 31) * 4;
            int gk0 = c * 32 + 2 * kp, gk1 = gk0 + 1;
            float4 v0 = *(const float4*)&W2[gk0 * DIMH + c4];
            float4 v1 = *(const float4*)&W2[gk1 * DIMH + c4];
            float h0x = __bfloat162float(__float2bfloat16_rn(v0.x));
            float h0y = __bfloat162float(__float2bfloat16_rn(v0.y));
            float h0z = __bfloat162float(__float2bfloat16_rn(v0.z));
            float h0w = __bfloat162float(__float2bfloat16_rn(v0.w));
            float h1x = __bfloat162float(__float2bfloat16_rn(v1.x));
            float h1y = __bfloat162float(__float2bfloat16_rn(v1.y));
            float h1z = __bfloat162float(__float2bfloat16_rn(v1.z));
            float h1w = __bfloat162float(__float2bfloat16_rn(v1.w));
            Bh[kp * BST + c4]     = pack_bf16(h0x, h1x);
            Bh[kp * BST + c4 + 1] = pack_bf16(h0y, h1y);
            Bh[kp * BST + c4 + 2] = pack_bf16(h0z, h1z);
            Bh[kp * BST + c4 + 3] = pack_bf16(h0w, h1w);
            Bl[kp * BST + c4]     = pack_bf16(v0.x - h0x, v1.x - h1x);
            Bl[kp * BST + c4 + 1] = pack_bf16(v0.y - h0y, v1.y - h1y);
            Bl[kp * BST + c4 + 2] = pack_bf16(v0.z - h0z, v1.z - h1z);
            Bl[kp * BST + c4 + 3] = pack_bf16(v0.w - h0w, v1.w - h1w);
        }
        __syncthreads();

        #pragma unroll
        for (int ks = 0; ks < 2; ks++) {
            const int kp0 = c * 16 + ks * 8;
            uint32_t a_hi[4][4], a_lo[4][4];
            #pragma unroll
            for (int mi = 0; mi < 4; mi++) {
                int rm = wm * 64 + mi * 16;
                a_hi[mi][0] = Hh[(rm + g    ) * HST + kp0 + tig    ];
                a_hi[mi][1] = Hh[(rm + g + 8) * HST + kp0 + tig    ];
                a_hi[mi][2] = Hh[(rm + g    ) * HST + kp0 + tig + 4];
                a_hi[mi][3] = Hh[(rm + g + 8) * HST + kp0 + tig + 4];
                a_lo[mi][0] = Hl[(rm + g    ) * HST + kp0 + tig    ];
                a_lo[mi][1] = Hl[(rm + g + 8) * HST + kp0 + tig    ];
                a_lo[mi][2] = Hl[(rm + g    ) * HST + kp0 + tig + 4];
                a_lo[mi][3] = Hl[(rm + g + 8) * HST + kp0 + tig + 4];
            }
            const int kb = ks * 8;
            #pragma unroll
            for (int ni = 0; ni < 4; ni++) {
                int cn = wn * 32 + ni * 8;
                uint32_t bh[2], bl[2];
                bh[0] = Bh[(kb + tig    ) * BST + cn + g];
                bh[1] = Bh[(kb + tig + 4) * BST + cn + g];
                bl[0] = Bl[(kb + tig    ) * BST + cn + g];
                bl[1] = Bl[(kb + tig + 4) * BST + cn + g];
                #pragma unroll
                for (int mi = 0; mi < 4; mi++) {
                    mma_bf16(acc[mi][ni], a_hi[mi], bh);
                    mma_bf16(acc[mi][ni], a_hi[mi], bl);
                    mma_bf16(acc[mi][ni], a_lo[mi], bh);
                }
            }
        }
    }

    // ---- epilogue2: bias + ReLU -> OUT ----
    float bb[4][2];
    #pragma unroll
    for (int ni = 0; ni < 4; ni++) {
        #pragma unroll
        for (int j = 0; j < 2; j++)
            bb[ni][j] = b2[wn * 32 + ni * 8 + 2 * tig + j];
    }
    #pragma unroll
    for (int mi = 0; mi < 4; mi++) {
        int r0 = row0 + wm * 64 + mi * 16 + g;
        int r1 = r0 + 8;
        #pragma unroll
        for (int ni = 0; ni < 4; ni++) {
            int c0 = wn * 32 + ni * 8 + 2 * tig;
            if (r0 < N_NODES) {
                float2 o;
                o.x = fmaxf(acc[mi][ni][0] + bb[ni][0], 0.0f);
                o.y = fmaxf(acc[mi][ni][1] + bb[ni][1], 0.0f);
                *(float2*)&OUT[r0 * DIMH + c0] = o;
            }
            if (r1 < N_NODES) {
                float2 o;
                o.x = fmaxf(acc[mi][ni][2] + bb[ni][0], 0.0f);
                o.y = fmaxf(acc[mi][ni][3] + bb[ni][1], 0.0f);
                *(float2*)&OUT[r1 * DIMH + c0] = o;
            }
        }
    }
}

// ---------------- pooling ----------------
__global__ void pool_kernel(const int* __restrict__ batch, const float* __restrict__ h,
                            float* __restrict__ pool) {
    int i = blockIdx.x * blockDim.x + threadIdx.x;
    if (i < N_NODES * DIMH) {
        int n = i >> 7, d = i & 127;
        atomicAdd(&pool[batch[n] * DIMH + d], h[i]);
    }
}

// ---------------- head ----------------
__global__ void head_kernel(const float* __restrict__ pool,
                            const float* __restrict__ l1w, const float* __restrict__ l1b,
                            const float* __restrict__ l2w, const float* __restrict__ l2b,
                            float* __restrict__ out) {
    __shared__ float hg[DIMH];
    __shared__ float o1[LIN1_DIM];
    int gph = blockIdx.x;
    int t = threadIdx.x;  // 128
    hg[t] = pool[gph * DIMH + t];
    __syncthreads();
    if (t < LIN1_DIM) {
        float s = l1b[t];
        #pragma unroll 8
        for (int k = 0; k < DIMH; k++) s += hg[k] * l1w[k * LIN1_DIM + t];
        o1[t] = fmaxf(s, 0.0f);
    }
    __syncthreads();
    if (t == 0) {
        float s = l2b[0];
        #pragma unroll 8
        for (int j = 0; j < LIN1_DIM; j++) s += o1[j] * l2w[j];
        out[gph] = 1.0f / (1.0f + expf(-s));
    }
}

// ---------------- launch ----------------
extern "C" void kernel_launch(void* const* d_in, const int* in_sizes, int n_in,
                              void* d_out, int out_size) {
    const float* x          = (const float*)d_in[0];
    const int*   edge_index = (const int*)d_in[1];
    const int*   batch      = (const int*)d_in[2];
    const float* w[3][7];
    const float* b2[3];
    for (int l = 0; l < 3; l++) {
        int base = 3 + l * 8;
        w[l][0] = (const float*)d_in[base + 0];
        w[l][1] = (const float*)d_in[base + 1];
        w[l][2] = (const float*)d_in[base + 2];
        w[l][3] = (const float*)d_in[base + 3];
        w[l][4] = (const float*)d_in[base + 4];
        w[l][5] = (const float*)d_in[base + 5];
        w[l][6] = (const float*)d_in[base + 6];
        b2[l]   = (const float*)d_in[base + 7];
    }
    const float* l1w = (const float*)d_in[27];
    const float* l1b = (const float*)d_in[28];
    const float* l2w = (const float*)d_in[29];
    const float* l2b = (const float*)d_in[30];
    float* out = (float*)d_out;

    const int* e_src = edge_index;
    const int* e_dst = edge_index + N_EDGES;

    static float* p_feat = nullptr;
    static float* p_a    = nullptr;
    static int*   p_cnt  = nullptr;
    static float* p_pool = nullptr;
    if (!p_feat) {
        cudaGetSymbolAddress((void**)&p_feat, g_feat);
        cudaGetSymbolAddress((void**)&p_a,    g_a);
        cudaGetSymbolAddress((void**)&p_cnt,  g_cnt);
        cudaGetSymbolAddress((void**)&p_pool, g_pool);
        cudaFuncSetAttribute(layer_gemm_kernel,
                             cudaFuncAttributeMaxDynamicSharedMemorySize,
                             SMEM_U32 * 4);
    }

    // ---- CSR build ----
    cudaMemsetAsync(p_cnt, 0, N_NODES * sizeof(int));
    count_kernel<<<(N_EDGES + 255) / 256, 256>>>(e_dst);
    scan_kernel<<<1, 1024>>>(N_NODES);
    scatter_kernel<<<(N_EDGES + 255) / 256, 256>>>(e_src, e_dst);

    // ---- pad x ----
    pad_x_kernel<<<(N_NODES * 64 + 255) / 256, 256>>>(x);

    const int GEMM_GRID = (N_NODES + 127) / 128;
    const int AGG_GRID  = (N_NODES * 32 + 255) / 256;
    const size_t SMEM   = SMEM_U32 * 4;

    // ---- 3 GIN layers: agg -> fused double-GEMM (in-place feat update) ----
    for (int l = 0; l < 3; l++) {
        int Kw1 = (l == 0) ? IN_DIM : DIMH;
        agg_kernel<<<AGG_GRID, 256>>>(p_feat, p_a);
        layer_gemm_kernel<<<GEMM_GRID, 256, SMEM>>>(p_a,
                                                    w[l][0], w[l][1], w[l][2], w[l][3],
                                                    w[l][4], w[l][5], w[l][6], b2[l],
                                                    p_feat, Kw1);
    }

    // ---- pool + head ----
    cudaMemsetAsync(p_pool, 0, N_GRAPHS * DIMH * sizeof(float));
    pool_kernel<<<(N_NODES * DIMH + 255) / 256, 256>>>(batch, p_feat, p_pool);
    head_kernel<<<N_GRAPHS, 128>>>(p_pool, l1w, l1b, l2w, l2b, out);
}

// round 8
// speedup vs baseline: 1.5717x; 1.1612x over previous
#include <cuda_runtime.h>
#include <cuda_bf16.h>
#include <math.h>
#include <stdint.h>

#define N_NODES 50000
#define N_EDGES 800000
#define N_GRAPHS 512
#define IN_DIM 126
#define DIMH 128
#define LIN1_DIM 64
#define BN_EPS 1e-5f

#define SCAN_NB 49   // ceil(50000/1024)

// ---------------- device scratch ----------------
__device__ float g_feat[N_NODES * DIMH];
__device__ float g_a[N_NODES * DIMH];
__device__ int   g_cnt[N_NODES];
__device__ int   g_off[N_NODES + 1];
__device__ int   g_cur[N_NODES];
__device__ int   g_srcs[N_EDGES];
__device__ float g_pool[N_GRAPHS * DIMH];
__device__ int   g_bsum[64];
__device__ int   g_bofs[64];
__device__ int   g_gstart[N_GRAPHS + 1];

// ---------------- CSR build ----------------
__global__ void count_kernel(const int* __restrict__ dst) {
    int i = blockIdx.x * blockDim.x + threadIdx.x;
    if (i < N_EDGES) atomicAdd(&g_cnt[dst[i]], 1);
}

// 49 blocks x 1024: per-block totals of g_cnt
__global__ void block_sum_kernel() {
    __shared__ int ws[32];
    int i = blockIdx.x * 1024 + threadIdx.x;
    int lane = threadIdx.x & 31, wid = threadIdx.x >> 5;
    int v = (i < N_NODES) ? g_cnt[i] : 0;
    #pragma unroll
    for (int o = 16; o > 0; o >>= 1) v += __shfl_down_sync(0xFFFFFFFFu, v, o);
    if (lane == 0) ws[wid] = v;
    __syncthreads();
    if (wid == 0) {
        int s = ws[lane];
        #pragma unroll
        for (int o = 16; o > 0; o >>= 1) s += __shfl_down_sync(0xFFFFFFFFu, s, o);
        if (lane == 0) g_bsum[blockIdx.x] = s;
    }
}

// 1 block x 64: exclusive scan of block sums; also writes g_off[N_NODES]
__global__ void scan_sums_kernel() {
    __shared__ int sh[64];
    int t = threadIdx.x;
    int v = (t < SCAN_NB) ? g_bsum[t] : 0;
    sh[t] = v;
    __syncthreads();
    #pragma unroll
    for (int o = 1; o < 64; o <<= 1) {
        int u = (t >= o) ? sh[t - o] : 0;
        __syncthreads();
        sh[t] += u;
        __syncthreads();
    }
    if (t < SCAN_NB) g_bofs[t] = sh[t] - v;   // exclusive
    if (t == 63) g_off[N_NODES] = sh[63];
}

// 49 blocks x 1024: per-block exclusive scan + block offset -> g_off, g_cur
__global__ void block_scan_kernel() {
    __shared__ int ws[32];
    int i = blockIdx.x * 1024 + threadIdx.x;
    int lane = threadIdx.x & 31, wid = threadIdx.x >> 5;
    int v = (i < N_NODES) ? g_cnt[i] : 0;
    int x = v;
    #pragma unroll
    for (int o = 1; o < 32; o <<= 1) {
        int t = __shfl_up_sync(0xFFFFFFFFu, x, o);
        if (lane >= o) x += t;
    }
    if (lane == 31) ws[wid] = x;
    __syncthreads();
    if (wid == 0) {
        int s = ws[lane];
        #pragma unroll
        for (int o = 1; o < 32; o <<= 1) {
            int t = __shfl_up_sync(0xFFFFFFFFu, s, o);
            if (lane >= o) s += t;
        }
        ws[lane] = s;
    }
    __syncthreads();
    if (i < N_NODES) {
        int excl = g_bofs[blockIdx.x] + x - v + (wid > 0 ? ws[wid - 1] : 0);
        g_off[i] = excl;
        g_cur[i] = excl;
    }
}

__global__ void scatter_kernel(const int* __restrict__ src, const int* __restrict__ dst) {
    int i = blockIdx.x * blockDim.x + threadIdx.x;
    if (i < N_EDGES) {
        int p = atomicAdd(&g_cur[dst[i]], 1);
        g_srcs[p] = src[i];
    }
}

// pad x [N,126] -> g_feat [N,128] (rows 8B-aligned)
__global__ void pad_x_kernel(const float* __restrict__ x) {
    int i = blockIdx.x * blockDim.x + threadIdx.x;
    if (i < N_NODES * 64) {
        int n = i >> 6, p = i & 63;
        float2 v = make_float2(0.f, 0.f);
        if (p < 63) v = *(const float2*)&x[n * IN_DIM + 2 * p];
        *(float2*)&g_feat[n * DIMH + 2 * p] = v;
    }
}

// graph start boundaries from sorted batch
__global__ void gstart_kernel(const int* __restrict__ batch) {
    int i = blockIdx.x * blockDim.x + threadIdx.x;
    if (i >= N_NODES) return;
    int b = batch[i];
    int bp = (i == 0) ? -1 : batch[i - 1];
    for (int gg = bp + 1; gg <= b; gg++) g_gstart[gg] = i;
    if (i == N_NODES - 1)
        for (int gg = b + 1; gg <= N_GRAPHS; gg++) g_gstart[gg] = N_NODES;
}

// ---------------- aggregation: warp per node, float4 lanes ----------------
__global__ __launch_bounds__(256) void agg_kernel(const float* __restrict__ F,
                                                  float* __restrict__ out) {
    int warp = (blockIdx.x * blockDim.x + threadIdx.x) >> 5;
    int lane = threadIdx.x & 31;
    if (warp >= N_NODES) return;
    int s = g_off[warp], e = g_off[warp + 1];
    float4 acc = *(const float4*)&F[warp * DIMH + lane * 4];
    for (int base = s; base < e; base += 32) {
        int cnt = min(32, e - base);
        int idx = (base + lane < e) ? g_srcs[base + lane] : 0;
        int j = 0;
        for (; j + 4 <= cnt; j += 4) {
            int s0 = __shfl_sync(0xFFFFFFFFu, idx, j);
            int s1 = __shfl_sync(0xFFFFFFFFu, idx, j + 1);
            int s2 = __shfl_sync(0xFFFFFFFFu, idx, j + 2);
            int s3 = __shfl_sync(0xFFFFFFFFu, idx, j + 3);
            float4 v0 = *(const float4*)&F[s0 * DIMH + lane * 4];
            float4 v1 = *(const float4*)&F[s1 * DIMH + lane * 4];
            float4 v2 = *(const float4*)&F[s2 * DIMH + lane * 4];
            float4 v3 = *(const float4*)&F[s3 * DIMH + lane * 4];
            acc.x += v0.x + v1.x + v2.x + v3.x;
            acc.y += v0.y + v1.y + v2.y + v3.y;
            acc.z += v0.z + v1.z + v2.z + v3.z;
            acc.w += v0.w + v1.w + v2.w + v3.w;
        }
        for (; j < cnt; j++) {
            int s0 = __shfl_sync(0xFFFFFFFFu, idx, j);
            float4 v = *(const float4*)&F[s0 * DIMH + lane * 4];
            acc.x += v.x; acc.y += v.y; acc.z += v.z; acc.w += v.w;
        }
    }
    *(float4*)&out[warp * DIMH + lane * 4] = acc;
}

// ---------------- bf16 helpers ----------------
__device__ __forceinline__ uint32_t pack_bf16(float a, float b) {
    __nv_bfloat162 p = __floats2bfloat162_rn(a, b);
    return *(uint32_t*)&p;
}
__device__ __forceinline__ void mma_bf16(float* c, const uint32_t* a, const uint32_t* b) {
    asm volatile(
        "mma.sync.aligned.m16n8k16.row.col.f32.bf16.bf16.f32 "
        "{%0,%1,%2,%3}, {%4,%5,%6,%7}, {%8,%9}, {%0,%1,%2,%3};\n"
        : "+f"(c[0]), "+f"(c[1]), "+f"(c[2]), "+f"(c[3])
        : "r"(a[0]), "r"(a[1]), "r"(a[2]), "r"(a[3]), "r"(b[0]), "r"(b[1]));
}

// ---------------- fused double-GEMM per GIN layer, 64-row tile -------------
// 8 warps: wm = wid&1 (2 x 32 rows), wn = wid>>1 (4 x 32 cols).
#define AST 20
#define BST 136
#define HST 68
#define SM_AH 0
#define SM_AL (64 * AST)
#define SM_BH (2 * 64 * AST)
#define SM_BL (SM_BH + 16 * BST)
#define SM_HH (SM_BH + 2 * 16 * BST)
#define SM_HL (SM_HH + 64 * HST)
#define SMEM_U32 (SM_HH + 2 * 64 * HST)

__global__ __launch_bounds__(256, 3) void layer_gemm_kernel(
    const float* __restrict__ A,
    const float* __restrict__ W1, const float* __restrict__ b1,
    const float* __restrict__ gamma, const float* __restrict__ beta,
    const float* __restrict__ mean, const float* __restrict__ var,
    const float* __restrict__ W2, const float* __restrict__ b2,
    float* __restrict__ OUT, int Kw1)
{
    extern __shared__ uint32_t sm[];
    uint32_t* Ah = sm + SM_AH;
    uint32_t* Al = sm + SM_AL;
    uint32_t* Bh = sm + SM_BH;
    uint32_t* Bl = sm + SM_BL;
    uint32_t* Hh = sm + SM_HH;
    uint32_t* Hl = sm + SM_HL;

    const int tid  = threadIdx.x;
    const int wid  = tid >> 5;
    const int lane = tid & 31;
    const int g    = lane >> 2;
    const int tig  = lane & 3;
    const int wm   = wid & 1;
    const int wn   = wid >> 1;
    const int row0 = blockIdx.x * 64;

    float acc[2][4][4];

    // =========== GEMM1: A(global, streamed) x W1 ===========
    #pragma unroll
    for (int mi = 0; mi < 2; mi++)
        #pragma unroll
        for (int ni = 0; ni < 4; ni++)
            #pragma unroll
            for (int r = 0; r < 4; r++) acc[mi][ni][r] = 0.0f;

    for (int c = 0; c < 4; c++) {
        // ---- A chunk 64x32 -> Ah/Al (2 float4/thread) ----
        #pragma unroll
        for (int l = 0; l < 2; l++) {
            int idx = tid + l * 256;
            int r = idx >> 3, c4 = (idx & 7) * 4;
            int gr = row0 + r;
            float4 v = make_float4(0.f, 0.f, 0.f, 0.f);
            if (gr < N_NODES) v = *(const float4*)&A[gr * DIMH + c * 32 + c4];
            float hx = __bfloat162float(__float2bfloat16_rn(v.x));
            float hy = __bfloat162float(__float2bfloat16_rn(v.y));
            float hz = __bfloat162float(__float2bfloat16_rn(v.z));
            float hw = __bfloat162float(__float2bfloat16_rn(v.w));
            int c2 = c4 >> 1;
            Ah[r * AST + c2]     = pack_bf16(hx, hy);
            Ah[r * AST + c2 + 1] = pack_bf16(hz, hw);
            Al[r * AST + c2]     = pack_bf16(v.x - hx, v.y - hy);
            Al[r * AST + c2 + 1] = pack_bf16(v.z - hz, v.w - hw);
        }
        // ---- W1 chunk 32x128 -> Bh/Bl ----
        #pragma unroll
        for (int l = 0; l < 2; l++) {
            int idx = tid + l * 256;
            int kp = idx >> 5;
            int c4 = (idx & 31) * 4;
            int gk0 = c * 32 + 2 * kp, gk1 = gk0 + 1;
            float4 v0 = make_float4(0.f, 0.f, 0.f, 0.f);
            float4 v1 = make_float4(0.f, 0.f, 0.f, 0.f);
            if (gk0 < Kw1) v0 = *(const float4*)&W1[gk0 * DIMH + c4];
            if (gk1 < Kw1) v1 = *(const float4*)&W1[gk1 * DIMH + c4];
            float h0x = __bfloat162float(__float2bfloat16_rn(v0.x));
            float h0y = __bfloat162float(__float2bfloat16_rn(v0.y));
            float h0z = __bfloat162float(__float2bfloat16_rn(v0.z));
            float h0w = __bfloat162float(__float2bfloat16_rn(v0.w));
            float h1x = __bfloat162float(__float2bfloat16_rn(v1.x));
            float h1y = __bfloat162float(__float2bfloat16_rn(v1.y));
            float h1z = __bfloat162float(__float2bfloat16_rn(v1.z));
            float h1w = __bfloat162float(__float2bfloat16_rn(v1.w));
            Bh[kp * BST + c4]     = pack_bf16(h0x, h1x);
            Bh[kp * BST + c4 + 1] = pack_bf16(h0y, h1y);
            Bh[kp * BST + c4 + 2] = pack_bf16(h0z, h1z);
            Bh[kp * BST + c4 + 3] = pack_bf16(h0w, h1w);
            Bl[kp * BST + c4]     = pack_bf16(v0.x - h0x, v1.x - h1x);
            Bl[kp * BST + c4 + 1] = pack_bf16(v0.y - h0y, v1.y - h1y);
            Bl[kp * BST + c4 + 2] = pack_bf16(v0.z - h0z, v1.z - h1z);
            Bl[kp * BST + c4 + 3] = pack_bf16(v0.w - h0w, v1.w - h1w);
        }
        __syncthreads();

        #pragma unroll
        for (int ks = 0; ks < 2; ks++) {
            const int kk2 = ks * 8;
            uint32_t a_hi[2][4], a_lo[2][4];
            #pragma unroll
            for (int mi = 0; mi < 2; mi++) {
                int rm = wm * 32 + mi * 16;
                a_hi[mi][0] = Ah[(rm + g    ) * AST + kk2 + tig    ];
                a_hi[mi][1] = Ah[(rm + g + 8) * AST + kk2 + tig    ];
                a_hi[mi][2] = Ah[(rm + g    ) * AST + kk2 + tig + 4];
                a_hi[mi][3] = Ah[(rm + g + 8) * AST + kk2 + tig + 4];
                a_lo[mi][0] = Al[(rm + g    ) * AST + kk2 + tig    ];
                a_lo[mi][1] = Al[(rm + g + 8) * AST + kk2 + tig    ];
                a_lo[mi][2] = Al[(rm + g    ) * AST + kk2 + tig + 4];
                a_lo[mi][3] = Al[(rm + g + 8) * AST + kk2 + tig + 4];
            }
            #pragma unroll
            for (int ni = 0; ni < 4; ni++) {
                int cn = wn * 32 + ni * 8;
                uint32_t bh[2], bl[2];
                bh[0] = Bh[(kk2 + tig    ) * BST + cn + g];
                bh[1] = Bh[(kk2 + tig + 4) * BST + cn + g];
                bl[0] = Bl[(kk2 + tig    ) * BST + cn + g];
                bl[1] = Bl[(kk2 + tig + 4) * BST + cn + g];
                #pragma unroll
                for (int mi = 0; mi < 2; mi++) {
                    mma_bf16(acc[mi][ni], a_hi[mi], bh);
                    mma_bf16(acc[mi][ni], a_hi[mi], bl);
                    mma_bf16(acc[mi][ni], a_lo[mi], bh);
                }
            }
        }
        __syncthreads();
    }

    // ---- epilogue1: BN+ReLU, repack h -> Hh/Hl ----
    {
        float sc[4][2], sh[4][2];
        #pragma unroll
        for (int ni = 0; ni < 4; ni++) {
            #pragma unroll
            for (int j = 0; j < 2; j++) {
                int col = wn * 32 + ni * 8 + 2 * tig + j;
                float s = gamma[col] * rsqrtf(var[col] + BN_EPS);
                sc[ni][j] = s;
                sh[ni][j] = beta[col] - mean[col] * s + b1[col] * s;
            }
        }
        #pragma unroll
        for (int mi = 0; mi < 2; mi++) {
            int r0 = wm * 32 + mi * 16 + g;
            int r1 = r0 + 8;
            #pragma unroll
            for (int ni = 0; ni < 4; ni++) {
                int kp = wn * 16 + ni * 4 + tig;
                float o00 = fmaxf(acc[mi][ni][0] * sc[ni][0] + sh[ni][0], 0.0f);
                float o01 = fmaxf(acc[mi][ni][1] * sc[ni][1] + sh[ni][1], 0.0f);
                float o10 = fmaxf(acc[mi][ni][2] * sc[ni][0] + sh[ni][0], 0.0f);
                float o11 = fmaxf(acc[mi][ni][3] * sc[ni][1] + sh[ni][1], 0.0f);
                float h00 = __bfloat162float(__float2bfloat16_rn(o00));
                float h01 = __bfloat162float(__float2bfloat16_rn(o01));
                float h10 = __bfloat162float(__float2bfloat16_rn(o10));
                float h11 = __bfloat162float(__float2bfloat16_rn(o11));
                Hh[r0 * HST + kp] = pack_bf16(h00, h01);
                Hl[r0 * HST + kp] = pack_bf16(o00 - h00, o01 - h01);
                Hh[r1 * HST + kp] = pack_bf16(h10, h11);
                Hl[r1 * HST + kp] = pack_bf16(o10 - h10, o11 - h11);
            }
        }
    }

    // =========== GEMM2: H(smem) x W2 ===========
    #pragma unroll
    for (int mi = 0; mi < 2; mi++)
        #pragma unroll
        for (int ni = 0; ni < 4; ni++)
            #pragma unroll
            for (int r = 0; r < 4; r++) acc[mi][ni][r] = 0.0f;

    for (int c = 0; c < 4; c++) {
        __syncthreads();
        // ---- W2 chunk 32x128 -> Bh/Bl ----
        #pragma unroll
        for (int l = 0; l < 2; l++) {
            int idx = tid + l * 256;
            int kp = idx >> 5;
            int c4 = (idx & 31) * 4;
            int gk0 = c * 32 + 2 * kp, gk1 = gk0 + 1;
            float4 v0 = *(const float4*)&W2[gk0 * DIMH + c4];
            float4 v1 = *(const float4*)&W2[gk1 * DIMH + c4];
            float h0x = __bfloat162float(__float2bfloat16_rn(v0.x));
            float h0y = __bfloat162float(__float2bfloat16_rn(v0.y));
            float h0z = __bfloat162float(__float2bfloat16_rn(v0.z));
            float h0w = __bfloat162float(__float2bfloat16_rn(v0.w));
            float h1x = __bfloat162float(__float2bfloat16_rn(v1.x));
            float h1y = __bfloat162float(__float2bfloat16_rn(v1.y));
            float h1z = __bfloat162float(__float2bfloat16_rn(v1.z));
            float h1w = __bfloat162float(__float2bfloat16_rn(v1.w));
            Bh[kp * BST + c4]     = pack_bf16(h0x, h1x);
            Bh[kp * BST + c4 + 1] = pack_bf16(h0y, h1y);
            Bh[kp * BST + c4 + 2] = pack_bf16(h0z, h1z);
            Bh[kp * BST + c4 + 3] = pack_bf16(h0w, h1w);
            Bl[kp * BST + c4]     = pack_bf16(v0.x - h0x, v1.x - h1x);
            Bl[kp * BST + c4 + 1] = pack_bf16(v0.y - h0y, v1.y - h1y);
            Bl[kp * BST + c4 + 2] = pack_bf16(v0.z - h0z, v1.z - h1z);
            Bl[kp * BST + c4 + 3] = pack_bf16(v0.w - h0w, v1.w - h1w);
        }
        __syncthreads();

        #pragma unroll
        for (int ks = 0; ks < 2; ks++) {
            const int kp0 = c * 16 + ks * 8;
            uint32_t a_hi[2][4], a_lo[2][4];
            #pragma unroll
            for (int mi = 0; mi < 2; mi++) {
                int rm = wm * 32 + mi * 16;
                a_hi[mi][0] = Hh[(rm + g    ) * HST + kp0 + tig    ];
                a_hi[mi][1] = Hh[(rm + g + 8) * HST + kp0 + tig    ];
                a_hi[mi][2] = Hh[(rm + g    ) * HST + kp0 + tig + 4];
                a_hi[mi][3] = Hh[(rm + g + 8) * HST + kp0 + tig + 4];
                a_lo[mi][0] = Hl[(rm + g    ) * HST + kp0 + tig    ];
                a_lo[mi][1] = Hl[(rm + g + 8) * HST + kp0 + tig    ];
                a_lo[mi][2] = Hl[(rm + g    ) * HST + kp0 + tig + 4];
                a_lo[mi][3] = Hl[(rm + g + 8) * HST + kp0 + tig + 4];
            }
            const int kb = ks * 8;
            #pragma unroll
            for (int ni = 0; ni < 4; ni++) {
                int cn = wn * 32 + ni * 8;
                uint32_t bh[2], bl[2];
                bh[0] = Bh[(kb + tig    ) * BST + cn + g];
                bh[1] = Bh[(kb + tig + 4) * BST + cn + g];
                bl[0] = Bl[(kb + tig    ) * BST + cn + g];
                bl[1] = Bl[(kb + tig + 4) * BST + cn + g];
                #pragma unroll
                for (int mi = 0; mi < 2; mi++) {
                    mma_bf16(acc[mi][ni], a_hi[mi], bh);
                    mma_bf16(acc[mi][ni], a_hi[mi], bl);
                    mma_bf16(acc[mi][ni], a_lo[mi], bh);
                }
            }
        }
    }

    // ---- epilogue2: bias + ReLU -> OUT ----
    float bb[4][2];
    #pragma unroll
    for (int ni = 0; ni < 4; ni++) {
        #pragma unroll
        for (int j = 0; j < 2; j++)
            bb[ni][j] = b2[wn * 32 + ni * 8 + 2 * tig + j];
    }
    #pragma unroll
    for (int mi = 0; mi < 2; mi++) {
        int r0 = row0 + wm * 32 + mi * 16 + g;
        int r1 = r0 + 8;
        #pragma unroll
        for (int ni = 0; ni < 4; ni++) {
            int c0 = wn * 32 + ni * 8 + 2 * tig;
            if (r0 < N_NODES) {
                float2 o;
                o.x = fmaxf(acc[mi][ni][0] + bb[ni][0], 0.0f);
                o.y = fmaxf(acc[mi][ni][1] + bb[ni][1], 0.0f);
                *(float2*)&OUT[r0 * DIMH + c0] = o;
            }
            if (r1 < N_NODES) {
                float2 o;
                o.x = fmaxf(acc[mi][ni][2] + bb[ni][0], 0.0f);
                o.y = fmaxf(acc[mi][ni][3] + bb[ni][1], 0.0f);
                *(float2*)&OUT[r1 * DIMH + c0] = o;
            }
        }
    }
}

// ---------------- segment pooling (batch sorted, no atomics) ----------------
__global__ void pool_seg_kernel(const float* __restrict__ h, float* __restrict__ pool) {
    int gph = blockIdx.x;
    int t = threadIdx.x;  // 128
    int s = g_gstart[gph], e = g_gstart[gph + 1];
    float a0 = 0.f, a1 = 0.f;
    int r = s;
    for (; r + 2 <= e; r += 2) {
        a0 += h[r * DIMH + t];
        a1 += h[(r + 1) * DIMH + t];
    }
    if (r < e) a0 += h[r * DIMH + t];
    pool[gph * DIMH + t] = a0 + a1;
}

// ---------------- head ----------------
__global__ void head_kernel(const float* __restrict__ pool,
                            const float* __restrict__ l1w, const float* __restrict__ l1b,
                            const float* __restrict__ l2w, const float* __restrict__ l2b,
                            float* __restrict__ out) {
    __shared__ float hg[DIMH];
    __shared__ float o1[LIN1_DIM];
    int gph = blockIdx.x;
    int t = threadIdx.x;  // 128
    hg[t] = pool[gph * DIMH + t];
    __syncthreads();
    if (t < LIN1_DIM) {
        float s = l1b[t];
        #pragma unroll 8
        for (int k = 0; k < DIMH; k++) s += hg[k] * l1w[k * LIN1_DIM + t];
        o1[t] = fmaxf(s, 0.0f);
    }
    __syncthreads();
    if (t == 0) {
        float s = l2b[0];
        #pragma unroll 8
        for (int j = 0; j < LIN1_DIM; j++) s += o1[j] * l2w[j];
        out[gph] = 1.0f / (1.0f + expf(-s));
    }
}

// ---------------- launch ----------------
extern "C" void kernel_launch(void* const* d_in, const int* in_sizes, int n_in,
                              void* d_out, int out_size) {
    const float* x          = (const float*)d_in[0];
    const int*   edge_index = (const int*)d_in[1];
    const int*   batch      = (const int*)d_in[2];
    const float* w[3][7];
    const float* b2[3];
    for (int l = 0; l < 3; l++) {
        int base = 3 + l * 8;
        w[l][0] = (const float*)d_in[base + 0];
        w[l][1] = (const float*)d_in[base + 1];
        w[l][2] = (const float*)d_in[base + 2];
        w[l][3] = (const float*)d_in[base + 3];
        w[l][4] = (const float*)d_in[base + 4];
        w[l][5] = (const float*)d_in[base + 5];
        w[l][6] = (const float*)d_in[base + 6];
        b2[l]   = (const float*)d_in[base + 7];
    }
    const float* l1w = (const float*)d_in[27];
    const float* l1b = (const float*)d_in[28];
    const float* l2w = (const float*)d_in[29];
    const float* l2b = (const float*)d_in[30];
    float* out = (float*)d_out;

    const int* e_src = edge_index;
    const int* e_dst = edge_index + N_EDGES;

    static float* p_feat = nullptr;
    static float* p_a    = nullptr;
    static int*   p_cnt  = nullptr;
    static float* p_pool = nullptr;
    if (!p_feat) {
        cudaGetSymbolAddress((void**)&p_feat, g_feat);
        cudaGetSymbolAddress((void**)&p_a,    g_a);
        cudaGetSymbolAddress((void**)&p_cnt,  g_cnt);
        cudaGetSymbolAddress((void**)&p_pool, g_pool);
        cudaFuncSetAttribute(layer_gemm_kernel,
                             cudaFuncAttributeMaxDynamicSharedMemorySize,
                             SMEM_U32 * 4);
    }

    // ---- CSR build ----
    cudaMemsetAsync(p_cnt, 0, N_NODES * sizeof(int));
    count_kernel<<<(N_EDGES + 255) / 256, 256>>>(e_dst);
    block_sum_kernel<<<SCAN_NB, 1024>>>();
    scan_sums_kernel<<<1, 64>>>();
    block_scan_kernel<<<SCAN_NB, 1024>>>();
    scatter_kernel<<<(N_EDGES + 255) / 256, 256>>>(e_src, e_dst);

    // ---- pad x, graph boundaries ----
    pad_x_kernel<<<(N_NODES * 64 + 255) / 256, 256>>>(x);
    gstart_kernel<<<(N_NODES + 255) / 256, 256>>>(batch);

    const int GEMM_GRID = (N_NODES + 63) / 64;
    const int AGG_GRID  = (N_NODES * 32 + 255) / 256;
    const size_t SMEM   = SMEM_U32 * 4;

    // ---- 3 GIN layers: agg -> fused double-GEMM ----
    for (int l = 0; l < 3; l++) {
        int Kw1 = (l == 0) ? IN_DIM : DIMH;
        agg_kernel<<<AGG_GRID, 256>>>(p_feat, p_a);
        layer_gemm_kernel<<<GEMM_GRID, 256, SMEM>>>(p_a,
                                                    w[l][0], w[l][1], w[l][2], w[l][3],
                                                    w[l][4], w[l][5], w[l][6], b2[l],
                                                    p_feat, Kw1);
    }

    // ---- pool + head ----
    pool_seg_kernel<<<N_GRAPHS, 128>>>(p_feat, p_pool);
    head_kernel<<<N_GRAPHS, 128>>>(p_pool, l1w, l1b, l2w, l2b, out);
}

// round 9
// speedup vs baseline: 1.7864x; 1.1366x over previous
#include <cuda_runtime.h>
#include <cuda_fp16.h>
#include <math.h>
#include <stdint.h>

#define N_NODES 50000
#define N_EDGES 800000
#define N_GRAPHS 512
#define IN_DIM 126
#define DIMH 128
#define LIN1_DIM 64
#define BN_EPS 1e-5f

#define SCAN_NB 49   // ceil(50000/1024)
#define KPAIRS 64    // 128 k / 2 per u32

// ---------------- device scratch ----------------
__device__ float    g_feat[N_NODES * DIMH];
__device__ uint32_t g_ah[N_NODES * KPAIRS];    // agg output, fp16-hi plane (packed half2)
__device__ uint32_t g_al[N_NODES * KPAIRS];    // fp16-lo (residual) plane
__device__ uint32_t g_wsp[6 * KPAIRS * 128];   // pre-split weights (fp16 packed), slot-major
__device__ int      g_cnt[N_NODES];
__device__ int      g_off[N_NODES + 1];
__device__ int      g_cur[N_NODES];
__device__ int      g_srcs[N_EDGES];
__device__ float    g_pool[N_GRAPHS * DIMH];
__device__ int      g_bsum[64];
__device__ int      g_bofs[64];
__device__ int      g_gstart[N_GRAPHS + 1];

// ---------------- CSR build ----------------
__global__ void count_kernel(const int* __restrict__ dst) {
    int i = blockIdx.x * blockDim.x + threadIdx.x;
    if (i < N_EDGES) atomicAdd(&g_cnt[dst[i]], 1);
}

__global__ void block_sum_kernel() {
    __shared__ int ws[32];
    int i = blockIdx.x * 1024 + threadIdx.x;
    int lane = threadIdx.x & 31, wid = threadIdx.x >> 5;
    int v = (i < N_NODES) ? g_cnt[i] : 0;
    #pragma unroll
    for (int o = 16; o > 0; o >>= 1) v += __shfl_down_sync(0xFFFFFFFFu, v, o);
    if (lane == 0) ws[wid] = v;
    __syncthreads();
    if (wid == 0) {
        int s = ws[lane];
        #pragma unroll
        for (int o = 16; o > 0; o >>= 1) s += __shfl_down_sync(0xFFFFFFFFu, s, o);
        if (lane == 0) g_bsum[blockIdx.x] = s;
    }
}

__global__ void scan_sums_kernel() {
    __shared__ int sh[64];
    int t = threadIdx.x;
    int v = (t < SCAN_NB) ? g_bsum[t] : 0;
    sh[t] = v;
    __syncthreads();
    #pragma unroll
    for (int o = 1; o < 64; o <<= 1) {
        int u = (t >= o) ? sh[t - o] : 0;
        __syncthreads();
        sh[t] += u;
        __syncthreads();
    }
    if (t < SCAN_NB) g_bofs[t] = sh[t] - v;
    if (t == 63) g_off[N_NODES] = sh[63];
}

__global__ void block_scan_kernel() {
    __shared__ int ws[32];
    int i = blockIdx.x * 1024 + threadIdx.x;
    int lane = threadIdx.x & 31, wid = threadIdx.x >> 5;
    int v = (i < N_NODES) ? g_cnt[i] : 0;
    int x = v;
    #pragma unroll
    for (int o = 1; o < 32; o <<= 1) {
        int t = __shfl_up_sync(0xFFFFFFFFu, x, o);
        if (lane >= o) x += t;
    }
    if (lane == 31) ws[wid] = x;
    __syncthreads();
    if (wid == 0) {
        int s = ws[lane];
        #pragma unroll
        for (int o = 1; o < 32; o <<= 1) {
            int t = __shfl_up_sync(0xFFFFFFFFu, s, o);
            if (lane >= o) s += t;
        }
        ws[lane] = s;
    }
    __syncthreads();
    if (i < N_NODES) {
        int excl = g_bofs[blockIdx.x] + x - v + (wid > 0 ? ws[wid - 1] : 0);
        g_off[i] = excl;
        g_cur[i] = excl;
    }
}

__global__ void scatter_kernel(const int* __restrict__ src, const int* __restrict__ dst) {
    int i = blockIdx.x * blockDim.x + threadIdx.x;
    if (i < N_EDGES) {
        int p = atomicAdd(&g_cur[dst[i]], 1);
        g_srcs[p] = src[i];
    }
}

__global__ void pad_x_kernel(const float* __restrict__ x) {
    int i = blockIdx.x * blockDim.x + threadIdx.x;
    if (i < N_NODES * 64) {
        int n = i >> 6, p = i & 63;
        float2 v = make_float2(0.f, 0.f);
        if (p < 63) v = *(const float2*)&x[n * IN_DIM + 2 * p];
        *(float2*)&g_feat[n * DIMH + 2 * p] = v;
    }
}

__global__ void gstart_kernel(const int* __restrict__ batch) {
    int i = blockIdx.x * blockDim.x + threadIdx.x;
    if (i >= N_NODES) return;
    int b = batch[i];
    int bp = (i == 0) ? -1 : batch[i - 1];
    for (int gg = bp + 1; gg <= b; gg++) g_gstart[gg] = i;
    if (i == N_NODES - 1)
        for (int gg = b + 1; gg <= N_GRAPHS; gg++) g_gstart[gg] = N_NODES;
}

// ---------------- weight pre-split: fp32 [K,128] -> packed half2 [64kp,128] --
__global__ void wsplit_kernel(const float* __restrict__ w1a, const float* __restrict__ w2a,
                              const float* __restrict__ w1b, const float* __restrict__ w2b,
                              const float* __restrict__ w1c, const float* __restrict__ w2c,
                              int Kw1) {
    int slot = blockIdx.y;
    const float* w = (slot == 0) ? w1a : (slot == 1) ? w2a : (slot == 2) ? w1b
                   : (slot == 3) ? w2b : (slot == 4) ? w1c : w2c;
    int Kw = (slot == 0) ? Kw1 : DIMH;
    int i = blockIdx.x * blockDim.x + threadIdx.x;
    if (i >= KPAIRS * 128) return;
    int kp = i >> 7, n = i & 127;
    int k0 = 2 * kp, k1 = k0 + 1;
    float v0 = (k0 < Kw) ? w[k0 * DIMH + n] : 0.0f;
    float v1 = (k1 < Kw) ? w[k1 * DIMH + n] : 0.0f;
    __half2 h = __floats2half2_rn(v0, v1);
    g_wsp[slot * KPAIRS * 128 + i] = *(uint32_t*)&h;
}

// ---------------- aggregation: warp/node; emits fp16 hi/lo packed planes ----
__global__ __launch_bounds__(256) void agg_kernel(const float* __restrict__ F,
                                                  uint32_t* __restrict__ oh,
                                                  uint32_t* __restrict__ ol) {
    int warp = (blockIdx.x * blockDim.x + threadIdx.x) >> 5;
    int lane = threadIdx.x & 31;
    if (warp >= N_NODES) return;
    int s = g_off[warp], e = g_off[warp + 1];
    float4 acc = *(const float4*)&F[warp * DIMH + lane * 4];
    for (int base = s; base < e; base += 32) {
        int cnt = min(32, e - base);
        int idx = (base + lane < e) ? g_srcs[base + lane] : 0;
        int j = 0;
        for (; j + 4 <= cnt; j += 4) {
            int s0 = __shfl_sync(0xFFFFFFFFu, idx, j);
            int s1 = __shfl_sync(0xFFFFFFFFu, idx, j + 1);
            int s2 = __shfl_sync(0xFFFFFFFFu, idx, j + 2);
            int s3 = __shfl_sync(0xFFFFFFFFu, idx, j + 3);
            float4 v0 = *(const float4*)&F[s0 * DIMH + lane * 4];
            float4 v1 = *(const float4*)&F[s1 * DIMH + lane * 4];
            float4 v2 = *(const float4*)&F[s2 * DIMH + lane * 4];
            float4 v3 = *(const float4*)&F[s3 * DIMH + lane * 4];
            acc.x += v0.x + v1.x + v2.x + v3.x;
            acc.y += v0.y + v1.y + v2.y + v3.y;
            acc.z += v0.z + v1.z + v2.z + v3.z;
            acc.w += v0.w + v1.w + v2.w + v3.w;
        }
        for (; j < cnt; j++) {
            int s0 = __shfl_sync(0xFFFFFFFFu, idx, j);
            float4 v = *(const float4*)&F[s0 * DIMH + lane * 4];
            acc.x += v.x; acc.y += v.y; acc.z += v.z; acc.w += v.w;
        }
    }
    // split each fp32 into fp16 hi + fp16 residual
    __half hx = __float2half_rn(acc.x), hy = __float2half_rn(acc.y);
    __half hz = __float2half_rn(acc.z), hw = __float2half_rn(acc.w);
    float lx = acc.x - __half2float(hx), ly = acc.y - __half2float(hy);
    float lz = acc.z - __half2float(hz), lw = acc.w - __half2float(hw);
    __half2 h0 = __halves2half2(hx, hy), h1 = __halves2half2(hz, hw);
    __half2 l0 = __floats2half2_rn(lx, ly), l1 = __floats2half2_rn(lz, lw);
    uint2 hv = make_uint2(*(uint32_t*)&h0, *(uint32_t*)&h1);
    uint2 lv = make_uint2(*(uint32_t*)&l0, *(uint32_t*)&l1);
    *(uint2*)&oh[warp * KPAIRS + 2 * lane] = hv;
    *(uint2*)&ol[warp * KPAIRS + 2 * lane] = lv;
}

// ---------------- fp16 helpers ----------------
__device__ __forceinline__ uint32_t pack_f16x2(__half a, __half b) {
    __half2 p = __halves2half2(a, b);
    return *(uint32_t*)&p;
}
__device__ __forceinline__ void mma_f16(float* c, const uint32_t* a, const uint32_t* b) {
    asm volatile(
        "mma.sync.aligned.m16n8k16.row.col.f32.f16.f16.f32 "
        "{%0,%1,%2,%3}, {%4,%5,%6,%7}, {%8,%9}, {%0,%1,%2,%3};\n"
        : "+f"(c[0]), "+f"(c[1]), "+f"(c[2]), "+f"(c[3])
        : "r"(a[0]), "r"(a[1]), "r"(a[2]), "r"(a[3]), "r"(b[0]), "r"(b[1]));
}

// ---------------- fused double-GEMM per GIN layer, 64-row tile, fp16 2-term -
#define AST 20
#define BST 136
#define HST 68
#define SM_AH 0
#define SM_AL (64 * AST)
#define SM_B  (2 * 64 * AST)
#define SM_HH (SM_B + 16 * BST)
#define SM_HL (SM_HH + 64 * HST)
#define SMEM_U32 (SM_HH + 2 * 64 * HST)

__global__ __launch_bounds__(256, 3) void layer_gemm_kernel(
    const uint32_t* __restrict__ Ahg, const uint32_t* __restrict__ Alg,
    const uint32_t* __restrict__ W1p, const float* __restrict__ b1,
    const float* __restrict__ gamma, const float* __restrict__ beta,
    const float* __restrict__ mean, const float* __restrict__ var,
    const uint32_t* __restrict__ W2p, const float* __restrict__ b2,
    float* __restrict__ OUT)
{
    extern __shared__ uint32_t sm[];
    uint32_t* Ah = sm + SM_AH;
    uint32_t* Al = sm + SM_AL;
    uint32_t* B  = sm + SM_B;
    uint32_t* Hh = sm + SM_HH;
    uint32_t* Hl = sm + SM_HL;

    const int tid  = threadIdx.x;
    const int wid  = tid >> 5;
    const int lane = tid & 31;
    const int g    = lane >> 2;
    const int tig  = lane & 3;
    const int wm   = wid & 1;
    const int wn   = wid >> 1;
    const int row0 = blockIdx.x * 64;

    float acc[2][4][4];

    // =========== GEMM1: A(planes in global) x W1(pre-split) ===========
    #pragma unroll
    for (int mi = 0; mi < 2; mi++)
        #pragma unroll
        for (int ni = 0; ni < 4; ni++)
            #pragma unroll
            for (int r = 0; r < 4; r++) acc[mi][ni][r] = 0.0f;

    for (int c = 0; c < 4; c++) {
        // ---- A chunk: 64 rows x 16 kpairs x 2 planes, raw uint4 copies ----
        {
            int r = tid >> 2, kp4 = (tid & 3) * 4;
            int gr = row0 + r;
            uint4 vh = make_uint4(0, 0, 0, 0), vl = make_uint4(0, 0, 0, 0);
            if (gr < N_NODES) {
                vh = *(const uint4*)&Ahg[gr * KPAIRS + c * 16 + kp4];
                vl = *(const uint4*)&Alg[gr * KPAIRS + c * 16 + kp4];
            }
            *(uint4*)&Ah[r * AST + kp4] = vh;
            *(uint4*)&Al[r * AST + kp4] = vl;
        }
        // ---- W1 chunk: 16 kpairs x 128 n, raw uint4 copies ----
        #pragma unroll
        for (int l = 0; l < 2; l++) {
            int idx = tid + l * 256;
            int kp = idx >> 5;
            int c4 = (idx & 31) * 4;
            uint4 v = *(const uint4*)&W1p[(c * 16 + kp) * 128 + c4];
            *(uint4*)&B[kp * BST + c4] = v;
        }
        __syncthreads();

        #pragma unroll
        for (int ks = 0; ks < 2; ks++) {
            const int kk2 = ks * 8;
            uint32_t a_hi[2][4], a_lo[2][4];
            #pragma unroll
            for (int mi = 0; mi < 2; mi++) {
                int rm = wm * 32 + mi * 16;
                a_hi[mi][0] = Ah[(rm + g    ) * AST + kk2 + tig    ];
                a_hi[mi][1] = Ah[(rm + g + 8) * AST + kk2 + tig    ];
                a_hi[mi][2] = Ah[(rm + g    ) * AST + kk2 + tig + 4];
                a_hi[mi][3] = Ah[(rm + g + 8) * AST + kk2 + tig + 4];
                a_lo[mi][0] = Al[(rm + g    ) * AST + kk2 + tig    ];
                a_lo[mi][1] = Al[(rm + g + 8) * AST + kk2 + tig    ];
                a_lo[mi][2] = Al[(rm + g    ) * AST + kk2 + tig + 4];
                a_lo[mi][3] = Al[(rm + g + 8) * AST + kk2 + tig + 4];
            }
            #pragma unroll
            for (int ni = 0; ni < 4; ni++) {
                int cn = wn * 32 + ni * 8;
                uint32_t b[2];
                b[0] = B[(kk2 + tig    ) * BST + cn + g];
                b[1] = B[(kk2 + tig + 4) * BST + cn + g];
                #pragma unroll
                for (int mi = 0; mi < 2; mi++) {
                    mma_f16(acc[mi][ni], a_hi[mi], b);
                    mma_f16(acc[mi][ni], a_lo[mi], b);
                }
            }
        }
        __syncthreads();
    }

    // ---- epilogue1: BN+ReLU, split fp16 hi/lo, repack -> Hh/Hl ----
    {
        float sc[4][2], sh[4][2];
        #pragma unroll
        for (int ni = 0; ni < 4; ni++) {
            #pragma unroll
            for (int j = 0; j < 2; j++) {
                int col = wn * 32 + ni * 8 + 2 * tig + j;
                float s = gamma[col] * rsqrtf(var[col] + BN_EPS);
                sc[ni][j] = s;
                sh[ni][j] = beta[col] - mean[col] * s + b1[col] * s;
            }
        }
        #pragma unroll
        for (int mi = 0; mi < 2; mi++) {
            int r0 = wm * 32 + mi * 16 + g;
            int r1 = r0 + 8;
            #pragma unroll
            for (int ni = 0; ni < 4; ni++) {
                int kp = wn * 16 + ni * 4 + tig;
                float o00 = fmaxf(acc[mi][ni][0] * sc[ni][0] + sh[ni][0], 0.0f);
                float o01 = fmaxf(acc[mi][ni][1] * sc[ni][1] + sh[ni][1], 0.0f);
                float o10 = fmaxf(acc[mi][ni][2] * sc[ni][0] + sh[ni][0], 0.0f);
                float o11 = fmaxf(acc[mi][ni][3] * sc[ni][1] + sh[ni][1], 0.0f);
                __half h00 = __float2half_rn(o00), h01 = __float2half_rn(o01);
                __half h10 = __float2half_rn(o10), h11 = __float2half_rn(o11);
                __half2 l0 = __floats2half2_rn(o00 - __half2float(h00),
                                               o01 - __half2float(h01));
                __half2 l1 = __floats2half2_rn(o10 - __half2float(h10),
                                               o11 - __half2float(h11));
                Hh[r0 * HST + kp] = pack_f16x2(h00, h01);
                Hl[r0 * HST + kp] = *(uint32_t*)&l0;
                Hh[r1 * HST + kp] = pack_f16x2(h10, h11);
                Hl[r1 * HST + kp] = *(uint32_t*)&l1;
            }
        }
    }

    // =========== GEMM2: H(smem) x W2(pre-split) ===========
    #pragma unroll
    for (int mi = 0; mi < 2; mi++)
        #pragma unroll
        for (int ni = 0; ni < 4; ni++)
            #pragma unroll
            for (int r = 0; r < 4; r++) acc[mi][ni][r] = 0.0f;

    for (int c = 0; c < 4; c++) {
        __syncthreads();   // H writes visible (c==0) / prev-chunk B reads done
        #pragma unroll
        for (int l = 0; l < 2; l++) {
            int idx = tid + l * 256;
            int kp = idx >> 5;
            int c4 = (idx & 31) * 4;
            uint4 v = *(const uint4*)&W2p[(c * 16 + kp) * 128 + c4];
            *(uint4*)&B[kp * BST + c4] = v;
        }
        __syncthreads();

        #pragma unroll
        for (int ks = 0; ks < 2; ks++) {
            const int kp0 = c * 16 + ks * 8;
            uint32_t a_hi[2][4], a_lo[2][4];
            #pragma unroll
            for (int mi = 0; mi < 2; mi++) {
                int rm = wm * 32 + mi * 16;
                a_hi[mi][0] = Hh[(rm + g    ) * HST + kp0 + tig    ];
                a_hi[mi][1] = Hh[(rm + g + 8) * HST + kp0 + tig    ];
                a_hi[mi][2] = Hh[(rm + g    ) * HST + kp0 + tig + 4];
                a_hi[mi][3] = Hh[(rm + g + 8) * HST + kp0 + tig + 4];
                a_lo[mi][0] = Hl[(rm + g    ) * HST + kp0 + tig    ];
                a_lo[mi][1] = Hl[(rm + g + 8) * HST + kp0 + tig    ];
                a_lo[mi][2] = Hl[(rm + g    ) * HST + kp0 + tig + 4];
                a_lo[mi][3] = Hl[(rm + g + 8) * HST + kp0 + tig + 4];
            }
            const int kb = ks * 8;
            #pragma unroll
            for (int ni = 0; ni < 4; ni++) {
                int cn = wn * 32 + ni * 8;
                uint32_t b[2];
                b[0] = B[(kb + tig    ) * BST + cn + g];
                b[1] = B[(kb + tig + 4) * BST + cn + g];
                #pragma unroll
                for (int mi = 0; mi < 2; mi++) {
                    mma_f16(acc[mi][ni], a_hi[mi], b);
                    mma_f16(acc[mi][ni], a_lo[mi], b);
                }
            }
        }
    }

    // ---- epilogue2: bias + ReLU -> OUT (fp32) ----
    float bb[4][2];
    #pragma unroll
    for (int ni = 0; ni < 4; ni++) {
        #pragma unroll
        for (int j = 0; j < 2; j++)
            bb[ni][j] = b2[wn * 32 + ni * 8 + 2 * tig + j];
    }
    #pragma unroll
    for (int mi = 0; mi < 2; mi++) {
        int r0 = row0 + wm * 32 + mi * 16 + g;
        int r1 = r0 + 8;
        #pragma unroll
        for (int ni = 0; ni < 4; ni++) {
            int c0 = wn * 32 + ni * 8 + 2 * tig;
            if (r0 < N_NODES) {
                float2 o;
                o.x = fmaxf(acc[mi][ni][0] + bb[ni][0], 0.0f);
                o.y = fmaxf(acc[mi][ni][1] + bb[ni][1], 0.0f);
                *(float2*)&OUT[r0 * DIMH + c0] = o;
            }
            if (r1 < N_NODES) {
                float2 o;
                o.x = fmaxf(acc[mi][ni][2] + bb[ni][0], 0.0f);
                o.y = fmaxf(acc[mi][ni][3] + bb[ni][1], 0.0f);
                *(float2*)&OUT[r1 * DIMH + c0] = o;
            }
        }
    }
}

// ---------------- segment pooling (batch sorted, no atomics) ----------------
__global__ void pool_seg_kernel(const float* __restrict__ h, float* __restrict__ pool) {
    int gph = blockIdx.x;
    int t = threadIdx.x;  // 128
    int s = g_gstart[gph], e = g_gstart[gph + 1];
    float a0 = 0.f, a1 = 0.f;
    int r = s;
    for (; r + 2 <= e; r += 2) {
        a0 += h[r * DIMH + t];
        a1 += h[(r + 1) * DIMH + t];
    }
    if (r < e) a0 += h[r * DIMH + t];
    pool[gph * DIMH + t] = a0 + a1;
}

// ---------------- head ----------------
__global__ void head_kernel(const float* __restrict__ pool,
                            const float* __restrict__ l1w, const float* __restrict__ l1b,
                            const float* __restrict__ l2w, const float* __restrict__ l2b,
                            float* __restrict__ out) {
    __shared__ float hg[DIMH];
    __shared__ float o1[LIN1_DIM];
    int gph = blockIdx.x;
    int t = threadIdx.x;  // 128
    hg[t] = pool[gph * DIMH + t];
    __syncthreads();
    if (t < LIN1_DIM) {
        float s = l1b[t];
        #pragma unroll 8
        for (int k = 0; k < DIMH; k++) s += hg[k] * l1w[k * LIN1_DIM + t];
        o1[t] = fmaxf(s, 0.0f);
    }
    __syncthreads();
    if (t == 0) {
        float s = l2b[0];
        #pragma unroll 8
        for (int j = 0; j < LIN1_DIM; j++) s += o1[j] * l2w[j];
        out[gph] = 1.0f / (1.0f + expf(-s));
    }
}

// ---------------- launch ----------------
extern "C" void kernel_launch(void* const* d_in, const int* in_sizes, int n_in,
                              void* d_out, int out_size) {
    const float* x          = (const float*)d_in[0];
    const int*   edge_index = (const int*)d_in[1];
    const int*   batch      = (const int*)d_in[2];
    const float* w[3][7];
    const float* b2[3];
    for (int l = 0; l < 3; l++) {
        int base = 3 + l * 8;
        w[l][0] = (const float*)d_in[base + 0];
        w[l][1] = (const float*)d_in[base + 1];
        w[l][2] = (const float*)d_in[base + 2];
        w[l][3] = (const float*)d_in[base + 3];
        w[l][4] = (const float*)d_in[base + 4];
        w[l][5] = (const float*)d_in[base + 5];
        w[l][6] = (const float*)d_in[base + 6];
        b2[l]   = (const float*)d_in[base + 7];
    }
    const float* l1w = (const float*)d_in[27];
    const float* l1b = (const float*)d_in[28];
    const float* l2w = (const float*)d_in[29];
    const float* l2b = (const float*)d_in[30];
    float* out = (float*)d_out;

    const int* e_src = edge_index;
    const int* e_dst = edge_index + N_EDGES;

    static float*    p_feat = nullptr;
    static uint32_t* p_ah   = nullptr;
    static uint32_t* p_al   = nullptr;
    static uint32_t* p_wsp  = nullptr;
    static int*      p_cnt  = nullptr;
    static float*    p_pool = nullptr;
    if (!p_feat) {
        cudaGetSymbolAddress((void**)&p_feat, g_feat);
        cudaGetSymbolAddress((void**)&p_ah,   g_ah);
        cudaGetSymbolAddress((void**)&p_al,   g_al);
        cudaGetSymbolAddress((void**)&p_wsp,  g_wsp);
        cudaGetSymbolAddress((void**)&p_cnt,  g_cnt);
        cudaGetSymbolAddress((void**)&p_pool, g_pool);
        cudaFuncSetAttribute(layer_gemm_kernel,
                             cudaFuncAttributeMaxDynamicSharedMemorySize,
                             SMEM_U32 * 4);
    }

    // ---- CSR build ----
    cudaMemsetAsync(p_cnt, 0, N_NODES * sizeof(int));
    count_kernel<<<(N_EDGES + 255) / 256, 256>>>(e_dst);
    block_sum_kernel<<<SCAN_NB, 1024>>>();
    scan_sums_kernel<<<1, 64>>>();
    block_scan_kernel<<<SCAN_NB, 1024>>>();
    scatter_kernel<<<(N_EDGES + 255) / 256, 256>>>(e_src, e_dst);

    // ---- pad x, graph boundaries, weight pre-split ----
    pad_x_kernel<<<(N_NODES * 64 + 255) / 256, 256>>>(x);
    gstart_kernel<<<(N_NODES + 255) / 256, 256>>>(batch);
    {
        dim3 grid((KPAIRS * 128 + 255) / 256, 6);
        wsplit_kernel<<<grid, 256>>>(w[0][0], w[0][6], w[1][0], w[1][6],
                                     w[2][0], w[2][6], IN_DIM);
    }

    const int GEMM_GRID = (N_NODES + 63) / 64;
    const int AGG_GRID  = (N_NODES * 32 + 255) / 256;
    const size_t SMEM   = SMEM_U32 * 4;

    // ---- 3 GIN layers: agg (emits split planes) -> fused double-GEMM ----
    for (int l = 0; l < 3; l++) {
        agg_kernel<<<AGG_GRID, 256>>>(p_feat, p_ah, p_al);
        layer_gemm_kernel<<<GEMM_GRID, 256, SMEM>>>(
            p_ah, p_al,
            p_wsp + (2 * l) * KPAIRS * 128, w[l][1], w[l][2], w[l][3],
            w[l][4], w[l][5],
            p_wsp + (2 * l + 1) * KPAIRS * 128, b2[l],
            p_feat);
    }

    // ---- pool + head ----
    pool_seg_kernel<<<N_GRAPHS, 128>>>(p_feat, p_pool);
    head_kernel<<<N_GRAPHS, 128>>>(p_pool, l1w, l1b, l2w, l2b, out);
}

// round 10
// speedup vs baseline: 1.9508x; 1.0920x over previous
#include <cuda_runtime.h>
#include <cuda_fp16.h>
#include <math.h>
#include <stdint.h>

#define N_NODES 50000
#define N_EDGES 800000
#define N_GRAPHS 512
#define IN_DIM 126
#define DIMH 128
#define LIN1_DIM 64
#define BN_EPS 1e-5f

#define SCAN_NB 49   // ceil(50000/1024)
#define KPAIRS 64    // 128 k / 2 per u32

// ---------------- device scratch ----------------
__device__ uint32_t g_fh[N_NODES * KPAIRS];    // features, packed fp16 (half2)
__device__ uint32_t g_ah[N_NODES * KPAIRS];    // agg output hi plane
__device__ uint32_t g_al[N_NODES * KPAIRS];    // agg output lo (residual) plane
__device__ uint32_t g_wsp[6 * KPAIRS * 128];   // pre-split fp16 weights, slot-major
__device__ int      g_cnt[N_NODES];
__device__ int      g_off[N_NODES + 1];
__device__ int      g_cur[N_NODES];
__device__ int      g_srcs[N_EDGES];
__device__ float    g_pool[N_GRAPHS * DIMH];
__device__ int      g_bsum[64];
__device__ int      g_bofs[64];
__device__ int      g_gstart[N_GRAPHS + 1];

// ---------------- CSR build ----------------
__global__ void count_kernel(const int* __restrict__ dst) {
    int i = blockIdx.x * blockDim.x + threadIdx.x;
    if (i < N_EDGES) atomicAdd(&g_cnt[dst[i]], 1);
}

__global__ void block_sum_kernel() {
    __shared__ int ws[32];
    int i = blockIdx.x * 1024 + threadIdx.x;
    int lane = threadIdx.x & 31, wid = threadIdx.x >> 5;
    int v = (i < N_NODES) ? g_cnt[i] : 0;
    #pragma unroll
    for (int o = 16; o > 0; o >>= 1) v += __shfl_down_sync(0xFFFFFFFFu, v, o);
    if (lane == 0) ws[wid] = v;
    __syncthreads();
    if (wid == 0) {
        int s = ws[lane];
        #pragma unroll
        for (int o = 16; o > 0; o >>= 1) s += __shfl_down_sync(0xFFFFFFFFu, s, o);
        if (lane == 0) g_bsum[blockIdx.x] = s;
    }
}

__global__ void scan_sums_kernel() {
    __shared__ int sh[64];
    int t = threadIdx.x;
    int v = (t < SCAN_NB) ? g_bsum[t] : 0;
    sh[t] = v;
    __syncthreads();
    #pragma unroll
    for (int o = 1; o < 64; o <<= 1) {
        int u = (t >= o) ? sh[t - o] : 0;
        __syncthreads();
        sh[t] += u;
        __syncthreads();
    }
    if (t < SCAN_NB) g_bofs[t] = sh[t] - v;
    if (t == 63) g_off[N_NODES] = sh[63];
}

__global__ void block_scan_kernel() {
    __shared__ int ws[32];
    int i = blockIdx.x * 1024 + threadIdx.x;
    int lane = threadIdx.x & 31, wid = threadIdx.x >> 5;
    int v = (i < N_NODES) ? g_cnt[i] : 0;
    int x = v;
    #pragma unroll
    for (int o = 1; o < 32; o <<= 1) {
        int t = __shfl_up_sync(0xFFFFFFFFu, x, o);
        if (lane >= o) x += t;
    }
    if (lane == 31) ws[wid] = x;
    __syncthreads();
    if (wid == 0) {
        int s = ws[lane];
        #pragma unroll
        for (int o = 1; o < 32; o <<= 1) {
            int t = __shfl_up_sync(0xFFFFFFFFu, s, o);
            if (lane >= o) s += t;
        }
        ws[lane] = s;
    }
    __syncthreads();
    if (i < N_NODES) {
        int excl = g_bofs[blockIdx.x] + x - v + (wid > 0 ? ws[wid - 1] : 0);
        g_off[i] = excl;
        g_cur[i] = excl;
    }
}

__global__ void scatter_kernel(const int* __restrict__ src, const int* __restrict__ dst) {
    int i = blockIdx.x * blockDim.x + threadIdx.x;
    if (i < N_EDGES) {
        int p = atomicAdd(&g_cur[dst[i]], 1);
        g_srcs[p] = src[i];
    }
}

// pad x [N,126] fp32 -> g_fh [N,64] packed fp16
__global__ void pad_x_kernel(const float* __restrict__ x) {
    int i = blockIdx.x * blockDim.x + threadIdx.x;
    if (i < N_NODES * 64) {
        int n = i >> 6, p = i & 63;
        float2 v = make_float2(0.f, 0.f);
        if (p < 63) v = *(const float2*)&x[n * IN_DIM + 2 * p];
        __half2 h = __floats2half2_rn(v.x, v.y);
        g_fh[i] = *(uint32_t*)&h;
    }
}

__global__ void gstart_kernel(const int* __restrict__ batch) {
    int i = blockIdx.x * blockDim.x + threadIdx.x;
    if (i >= N_NODES) return;
    int b = batch[i];
    int bp = (i == 0) ? -1 : batch[i - 1];
    for (int gg = bp + 1; gg <= b; gg++) g_gstart[gg] = i;
    if (i == N_NODES - 1)
        for (int gg = b + 1; gg <= N_GRAPHS; gg++) g_gstart[gg] = N_NODES;
}

// ---------------- weight pre-split: fp32 [K,128] -> packed half2 ------------
__global__ void wsplit_kernel(const float* __restrict__ w1a, const float* __restrict__ w2a,
                              const float* __restrict__ w1b, const float* __restrict__ w2b,
                              const float* __restrict__ w1c, const float* __restrict__ w2c,
                              int Kw1) {
    int slot = blockIdx.y;
    const float* w = (slot == 0) ? w1a : (slot == 1) ? w2a : (slot == 2) ? w1b
                   : (slot == 3) ? w2b : (slot == 4) ? w1c : w2c;
    int Kw = (slot == 0) ? Kw1 : DIMH;
    int i = blockIdx.x * blockDim.x + threadIdx.x;
    if (i >= KPAIRS * 128) return;
    int kp = i >> 7, n = i & 127;
    int k0 = 2 * kp, k1 = k0 + 1;
    float v0 = (k0 < Kw) ? w[k0 * DIMH + n] : 0.0f;
    float v1 = (k1 < Kw) ? w[k1 * DIMH + n] : 0.0f;
    __half2 h = __floats2half2_rn(v0, v1);
    g_wsp[slot * KPAIRS * 128 + i] = *(uint32_t*)&h;
}

// ---------------- aggregation: warp/node over fp16 feat; emits hi/lo planes -
__global__ __launch_bounds__(256) void agg_kernel(const uint32_t* __restrict__ F,
                                                  uint32_t* __restrict__ oh,
                                                  uint32_t* __restrict__ ol) {
    int warp = (blockIdx.x * blockDim.x + threadIdx.x) >> 5;
    int lane = threadIdx.x & 31;
    if (warp >= N_NODES) return;
    int s = g_off[warp], e = g_off[warp + 1];
    // lane owns features 4*lane..4*lane+3 (two packed u32 at 2*lane, 2*lane+1)
    float4 acc;
    {
        uint2 v = *(const uint2*)&F[warp * KPAIRS + 2 * lane];
        float2 a = __half22float2(*(__half2*)&v.x);
        float2 b = __half22float2(*(__half2*)&v.y);
        acc = make_float4(a.x, a.y, b.x, b.y);
    }
    for (int base = s; base < e; base += 32) {
        int cnt = min(32, e - base);
        int idx = (base + lane < e) ? g_srcs[base + lane] : 0;
        int j = 0;
        for (; j + 4 <= cnt; j += 4) {
            int s0 = __shfl_sync(0xFFFFFFFFu, idx, j);
            int s1 = __shfl_sync(0xFFFFFFFFu, idx, j + 1);
            int s2 = __shfl_sync(0xFFFFFFFFu, idx, j + 2);
            int s3 = __shfl_sync(0xFFFFFFFFu, idx, j + 3);
            uint2 u0 = *(const uint2*)&F[s0 * KPAIRS + 2 * lane];
            uint2 u1 = *(const uint2*)&F[s1 * KPAIRS + 2 * lane];
            uint2 u2 = *(const uint2*)&F[s2 * KPAIRS + 2 * lane];
            uint2 u3 = *(const uint2*)&F[s3 * KPAIRS + 2 * lane];
            float2 a0 = __half22float2(*(__half2*)&u0.x), b0 = __half22float2(*(__half2*)&u0.y);
            float2 a1 = __half22float2(*(__half2*)&u1.x), b1 = __half22float2(*(__half2*)&u1.y);
            float2 a2 = __half22float2(*(__half2*)&u2.x), b2 = __half22float2(*(__half2*)&u2.y);
            float2 a3 = __half22float2(*(__half2*)&u3.x), b3 = __half22float2(*(__half2*)&u3.y);
            acc.x += (a0.x + a1.x) + (a2.x + a3.x);
            acc.y += (a0.y + a1.y) + (a2.y + a3.y);
            acc.z += (b0.x + b1.x) + (b2.x + b3.x);
            acc.w += (b0.y + b1.y) + (b2.y + b3.y);
        }
        for (; j < cnt; j++) {
            int s0 = __shfl_sync(0xFFFFFFFFu, idx, j);
            uint2 u = *(const uint2*)&F[s0 * KPAIRS + 2 * lane];
            float2 a = __half22float2(*(__half2*)&u.x), b = __half22float2(*(__half2*)&u.y);
            acc.x += a.x; acc.y += a.y; acc.z += b.x; acc.w += b.y;
        }
    }
    // split fp32 acc into fp16 hi + fp16 residual
    __half hx = __float2half_rn(acc.x), hy = __float2half_rn(acc.y);
    __half hz = __float2half_rn(acc.z), hw = __float2half_rn(acc.w);
    __half2 h0 = __halves2half2(hx, hy), h1 = __halves2half2(hz, hw);
    __half2 l0 = __floats2half2_rn(acc.x - __half2float(hx), acc.y - __half2float(hy));
    __half2 l1 = __floats2half2_rn(acc.z - __half2float(hz), acc.w - __half2float(hw));
    uint2 hv = make_uint2(*(uint32_t*)&h0, *(uint32_t*)&h1);
    uint2 lv = make_uint2(*(uint32_t*)&l0, *(uint32_t*)&l1);
    *(uint2*)&oh[warp * KPAIRS + 2 * lane] = hv;
    *(uint2*)&ol[warp * KPAIRS + 2 * lane] = lv;
}

// ---------------- fp16 helpers ----------------
__device__ __forceinline__ uint32_t pack_f16x2(__half a, __half b) {
    __half2 p = __halves2half2(a, b);
    return *(uint32_t*)&p;
}
__device__ __forceinline__ void mma_f16(float* c, const uint32_t* a, const uint32_t* b) {
    asm volatile(
        "mma.sync.aligned.m16n8k16.row.col.f32.f16.f16.f32 "
        "{%0,%1,%2,%3}, {%4,%5,%6,%7}, {%8,%9}, {%0,%1,%2,%3};\n"
        : "+f"(c[0]), "+f"(c[1]), "+f"(c[2]), "+f"(c[3])
        : "r"(a[0]), "r"(a[1]), "r"(a[2]), "r"(a[3]), "r"(b[0]), "r"(b[1]));
}

// ---------------- fused double-GEMM per GIN layer, 64-row tile, fp16 --------
#define AST 20
#define BST 136
#define HST 68
#define SM_AH 0
#define SM_AL (64 * AST)
#define SM_B  (2 * 64 * AST)
#define SM_HH (SM_B + 16 * BST)
#define SM_HL (SM_HH + 64 * HST)
#define SMEM_U32 (SM_HH + 2 * 64 * HST)

__global__ __launch_bounds__(256, 3) void layer_gemm_kernel(
    const uint32_t* __restrict__ Ahg, const uint32_t* __restrict__ Alg,
    const uint32_t* __restrict__ W1p, const float* __restrict__ b1,
    const float* __restrict__ gamma, const float* __restrict__ beta,
    const float* __restrict__ mean, const float* __restrict__ var,
    const uint32_t* __restrict__ W2p, const float* __restrict__ b2,
    uint32_t* __restrict__ OUT16)
{
    extern __shared__ uint32_t sm[];
    uint32_t* Ah = sm + SM_AH;
    uint32_t* Al = sm + SM_AL;
    uint32_t* B  = sm + SM_B;
    uint32_t* Hh = sm + SM_HH;
    uint32_t* Hl = sm + SM_HL;

    const int tid  = threadIdx.x;
    const int wid  = tid >> 5;
    const int lane = tid & 31;
    const int g    = lane >> 2;
    const int tig  = lane & 3;
    const int wm   = wid & 1;
    const int wn   = wid >> 1;
    const int row0 = blockIdx.x * 64;

    float acc[2][4][4];

    // =========== GEMM1 ===========
    #pragma unroll
    for (int mi = 0; mi < 2; mi++)
        #pragma unroll
        for (int ni = 0; ni < 4; ni++)
            #pragma unroll
            for (int r = 0; r < 4; r++) acc[mi][ni][r] = 0.0f;

    for (int c = 0; c < 4; c++) {
        {
            int r = tid >> 2, kp4 = (tid & 3) * 4;
            int gr = row0 + r;
            uint4 vh = make_uint4(0, 0, 0, 0), vl = make_uint4(0, 0, 0, 0);
            if (gr < N_NODES) {
                vh = *(const uint4*)&Ahg[gr * KPAIRS + c * 16 + kp4];
                vl = *(const uint4*)&Alg[gr * KPAIRS + c * 16 + kp4];
            }
            *(uint4*)&Ah[r * AST + kp4] = vh;
            *(uint4*)&Al[r * AST + kp4] = vl;
        }
        #pragma unroll
        for (int l = 0; l < 2; l++) {
            int idx = tid + l * 256;
            int kp = idx >> 5;
            int c4 = (idx & 31) * 4;
            uint4 v = *(const uint4*)&W1p[(c * 16 + kp) * 128 + c4];
            *(uint4*)&B[kp * BST + c4] = v;
        }
        __syncthreads();

        #pragma unroll
        for (int ks = 0; ks < 2; ks++) {
            const int kk2 = ks * 8;
            uint32_t a_hi[2][4], a_lo[2][4];
            #pragma unroll
            for (int mi = 0; mi < 2; mi++) {
                int rm = wm * 32 + mi * 16;
                a_hi[mi][0] = Ah[(rm + g    ) * AST + kk2 + tig    ];
                a_hi[mi][1] = Ah[(rm + g + 8) * AST + kk2 + tig    ];
                a_hi[mi][2] = Ah[(rm + g    ) * AST + kk2 + tig + 4];
                a_hi[mi][3] = Ah[(rm + g + 8) * AST + kk2 + tig + 4];
                a_lo[mi][0] = Al[(rm + g    ) * AST + kk2 + tig    ];
                a_lo[mi][1] = Al[(rm + g + 8) * AST + kk2 + tig    ];
                a_lo[mi][2] = Al[(rm + g    ) * AST + kk2 + tig + 4];
                a_lo[mi][3] = Al[(rm + g + 8) * AST + kk2 + tig + 4];
            }
            #pragma unroll
            for (int ni = 0; ni < 4; ni++) {
                int cn = wn * 32 + ni * 8;
                uint32_t b[2];
                b[0] = B[(kk2 + tig    ) * BST + cn + g];
                b[1] = B[(kk2 + tig + 4) * BST + cn + g];
                #pragma unroll
                for (int mi = 0; mi < 2; mi++) {
                    mma_f16(acc[mi][ni], a_hi[mi], b);
                    mma_f16(acc[mi][ni], a_lo[mi], b);
                }
            }
        }
        __syncthreads();
    }

    // ---- epilogue1: BN+ReLU, split hi/lo -> Hh/Hl ----
    {
        float sc[4][2], sh[4][2];
        #pragma unroll
        for (int ni = 0; ni < 4; ni++) {
            #pragma unroll
            for (int j = 0; j < 2; j++) {
                int col = wn * 32 + ni * 8 + 2 * tig + j;
                float s = gamma[col] * rsqrtf(var[col] + BN_EPS);
                sc[ni][j] = s;
                sh[ni][j] = beta[col] - mean[col] * s + b1[col] * s;
            }
        }
        #pragma unroll
        for (int mi = 0; mi < 2; mi++) {
            int r0 = wm * 32 + mi * 16 + g;
            int r1 = r0 + 8;
            #pragma unroll
            for (int ni = 0; ni < 4; ni++) {
                int kp = wn * 16 + ni * 4 + tig;
                float o00 = fmaxf(acc[mi][ni][0] * sc[ni][0] + sh[ni][0], 0.0f);
                float o01 = fmaxf(acc[mi][ni][1] * sc[ni][1] + sh[ni][1], 0.0f);
                float o10 = fmaxf(acc[mi][ni][2] * sc[ni][0] + sh[ni][0], 0.0f);
                float o11 = fmaxf(acc[mi][ni][3] * sc[ni][1] + sh[ni][1], 0.0f);
                __half h00 = __float2half_rn(o00), h01 = __float2half_rn(o01);
                __half h10 = __float2half_rn(o10), h11 = __float2half_rn(o11);
                __half2 l0 = __floats2half2_rn(o00 - __half2float(h00),
                                               o01 - __half2float(h01));
                __half2 l1 = __floats2half2_rn(o10 - __half2float(h10),
                                               o11 - __half2float(h11));
                Hh[r0 * HST + kp] = pack_f16x2(h00, h01);
                Hl[r0 * HST + kp] = *(uint32_t*)&l0;
                Hh[r1 * HST + kp] = pack_f16x2(h10, h11);
                Hl[r1 * HST + kp] = *(uint32_t*)&l1;
            }
        }
    }

    // =========== GEMM2 ===========
    #pragma unroll
    for (int mi = 0; mi < 2; mi++)
        #pragma unroll
        for (int ni = 0; ni < 4; ni++)
            #pragma unroll
            for (int r = 0; r < 4; r++) acc[mi][ni][r] = 0.0f;

    for (int c = 0; c < 4; c++) {
        __syncthreads();
        #pragma unroll
        for (int l = 0; l < 2; l++) {
            int idx = tid + l * 256;
            int kp = idx >> 5;
            int c4 = (idx & 31) * 4;
            uint4 v = *(const uint4*)&W2p[(c * 16 + kp) * 128 + c4];
            *(uint4*)&B[kp * BST + c4] = v;
        }
        __syncthreads();

        #pragma unroll
        for (int ks = 0; ks < 2; ks++) {
            const int kp0 = c * 16 + ks * 8;
            uint32_t a_hi[2][4], a_lo[2][4];
            #pragma unroll
            for (int mi = 0; mi < 2; mi++) {
                int rm = wm * 32 + mi * 16;
                a_hi[mi][0] = Hh[(rm + g    ) * HST + kp0 + tig    ];
                a_hi[mi][1] = Hh[(rm + g + 8) * HST + kp0 + tig    ];
                a_hi[mi][2] = Hh[(rm + g    ) * HST + kp0 + tig + 4];
                a_hi[mi][3] = Hh[(rm + g + 8) * HST + kp0 + tig + 4];
                a_lo[mi][0] = Hl[(rm + g    ) * HST + kp0 + tig    ];
                a_lo[mi][1] = Hl[(rm + g + 8) * HST + kp0 + tig    ];
                a_lo[mi][2] = Hl[(rm + g    ) * HST + kp0 + tig + 4];
                a_lo[mi][3] = Hl[(rm + g + 8) * HST + kp0 + tig + 4];
            }
            const int kb = ks * 8;
            #pragma unroll
            for (int ni = 0; ni < 4; ni++) {
                int cn = wn * 32 + ni * 8;
                uint32_t b[2];
                b[0] = B[(kb + tig    ) * BST + cn + g];
                b[1] = B[(kb + tig + 4) * BST + cn + g];
                #pragma unroll
                for (int mi = 0; mi < 2; mi++) {
                    mma_f16(acc[mi][ni], a_hi[mi], b);
                    mma_f16(acc[mi][ni], a_lo[mi], b);
                }
            }
        }
    }

    // ---- epilogue2: bias + ReLU -> packed fp16 OUT ----
    float bb[4][2];
    #pragma unroll
    for (int ni = 0; ni < 4; ni++) {
        #pragma unroll
        for (int j = 0; j < 2; j++)
            bb[ni][j] = b2[wn * 32 + ni * 8 + 2 * tig + j];
    }
    #pragma unroll
    for (int mi = 0; mi < 2; mi++) {
        int r0 = row0 + wm * 32 + mi * 16 + g;
        int r1 = r0 + 8;
        #pragma unroll
        for (int ni = 0; ni < 4; ni++) {
            int c0 = wn * 32 + ni * 8 + 2 * tig;   // even
            int kp = c0 >> 1;
            if (r0 < N_NODES) {
                __half2 o = __floats2half2_rn(
                    fmaxf(acc[mi][ni][0] + bb[ni][0], 0.0f),
                    fmaxf(acc[mi][ni][1] + bb[ni][1], 0.0f));
                OUT16[r0 * KPAIRS + kp] = *(uint32_t*)&o;
            }
            if (r1 < N_NODES) {
                __half2 o = __floats2half2_rn(
                    fmaxf(acc[mi][ni][2] + bb[ni][0], 0.0f),
                    fmaxf(acc[mi][ni][3] + bb[ni][1], 0.0f));
                OUT16[r1 * KPAIRS + kp] = *(uint32_t*)&o;
            }
        }
    }
}

// ---------------- segment pooling over fp16 features ------------------------
__global__ void pool_seg_kernel(const uint32_t* __restrict__ h, float* __restrict__ pool) {
    int gph = blockIdx.x;
    int t = threadIdx.x;       // 0..127 -> feature t
    int u = t >> 1, hi = t & 1;
    int s = g_gstart[gph], e = g_gstart[gph + 1];
    float a0 = 0.f, a1 = 0.f;
    int r = s;
    for (; r + 2 <= e; r += 2) {
        uint32_t v0 = h[r * KPAIRS + u];
        uint32_t v1 = h[(r + 1) * KPAIRS + u];
        float2 f0 = __half22float2(*(__half2*)&v0);
        float2 f1 = __half22float2(*(__half2*)&v1);
        a0 += hi ? f0.y : f0.x;
        a1 += hi ? f1.y : f1.x;
    }
    if (r < e) {
        uint32_t v = h[r * KPAIRS + u];
        float2 f = __half22float2(*(__half2*)&v);
        a0 += hi ? f.y : f.x;
    }
    pool[gph * DIMH + t] = a0 + a1;
}

// ---------------- head ----------------
__global__ void head_kernel(const float* __restrict__ pool,
                            const float* __restrict__ l1w, const float* __restrict__ l1b,
                            const float* __restrict__ l2w, const float* __restrict__ l2b,
                            float* __restrict__ out) {
    __shared__ float hg[DIMH];
    __shared__ float o1[LIN1_DIM];
    int gph = blockIdx.x;
    int t = threadIdx.x;  // 128
    hg[t] = pool[gph * DIMH + t];
    __syncthreads();
    if (t < LIN1_DIM) {
        float s = l1b[t];
        #pragma unroll 8
        for (int k = 0; k < DIMH; k++) s += hg[k] * l1w[k * LIN1_DIM + t];
        o1[t] = fmaxf(s, 0.0f);
    }
    __syncthreads();
    if (t == 0) {
        float s = l2b[0];
        #pragma unroll 8
        for (int j = 0; j < LIN1_DIM; j++) s += o1[j] * l2w[j];
        out[gph] = 1.0f / (1.0f + expf(-s));
    }
}

// ---------------- launch ----------------
extern "C" void kernel_launch(void* const* d_in, const int* in_sizes, int n_in,
                              void* d_out, int out_size) {
    const float* x          = (const float*)d_in[0];
    const int*   edge_index = (const int*)d_in[1];
    const int*   batch      = (const int*)d_in[2];
    const float* w[3][7];
    const float* b2[3];
    for (int l = 0; l < 3; l++) {
        int base = 3 + l * 8;
        w[l][0] = (const float*)d_in[base + 0];
        w[l][1] = (const float*)d_in[base + 1];
        w[l][2] = (const float*)d_in[base + 2];
        w[l][3] = (const float*)d_in[base + 3];
        w[l][4] = (const float*)d_in[base + 4];
        w[l][5] = (const float*)d_in[base + 5];
        w[l][6] = (const float*)d_in[base + 6];
        b2[l]   = (const float*)d_in[base + 7];
    }
    const float* l1w = (const float*)d_in[27];
    const float* l1b = (const float*)d_in[28];
    const float* l2w = (const float*)d_in[29];
    const float* l2b = (const float*)d_in[30];
    float* out = (float*)d_out;

    const int* e_src = edge_index;
    const int* e_dst = edge_index + N_EDGES;

    static uint32_t* p_fh   = nullptr;
    static uint32_t* p_ah   = nullptr;
    static uint32_t* p_al   = nullptr;
    static uint32_t* p_wsp  = nullptr;
    static int*      p_cnt  = nullptr;
    static float*    p_pool = nullptr;
    if (!p_fh) {
        cudaGetSymbolAddress((void**)&p_fh,   g_fh);
        cudaGetSymbolAddress((void**)&p_ah,   g_ah);
        cudaGetSymbolAddress((void**)&p_al,   g_al);
        cudaGetSymbolAddress((void**)&p_wsp,  g_wsp);
        cudaGetSymbolAddress((void**)&p_cnt,  g_cnt);
        cudaGetSymbolAddress((void**)&p_pool, g_pool);
        cudaFuncSetAttribute(layer_gemm_kernel,
                             cudaFuncAttributeMaxDynamicSharedMemorySize,
                             SMEM_U32 * 4);
    }

    // ---- CSR build ----
    cudaMemsetAsync(p_cnt, 0, N_NODES * sizeof(int));
    count_kernel<<<(N_EDGES + 255) / 256, 256>>>(e_dst);
    block_sum_kernel<<<SCAN_NB, 1024>>>();
    scan_sums_kernel<<<1, 64>>>();
    block_scan_kernel<<<SCAN_NB, 1024>>>();
    scatter_kernel<<<(N_EDGES + 255) / 256, 256>>>(e_src, e_dst);

    // ---- pad x, graph boundaries, weight pre-split ----
    pad_x_kernel<<<(N_NODES * 64 + 255) / 256, 256>>>(x);
    gstart_kernel<<<(N_NODES + 255) / 256, 256>>>(batch);
    {
        dim3 grid((KPAIRS * 128 + 255) / 256, 6);
        wsplit_kernel<<<grid, 256>>>(w[0][0], w[0][6], w[1][0], w[1][6],
                                     w[2][0], w[2][6], IN_DIM);
    }

    const int GEMM_GRID = (N_NODES + 63) / 64;
    const int AGG_GRID  = (N_NODES * 32 + 255) / 256;
    const size_t SMEM   = SMEM_U32 * 4;

    // ---- 3 GIN layers ----
    for (int l = 0; l < 3; l++) {
        agg_kernel<<<AGG_GRID, 256>>>(p_fh, p_ah, p_al);
        layer_gemm_kernel<<<GEMM_GRID, 256, SMEM>>>(
            p_ah, p_al,
            p_wsp + (2 * l) * KPAIRS * 128, w[l][1], w[l][2], w[l][3],
            w[l][4], w[l][5],
            p_wsp + (2 * l + 1) * KPAIRS * 128, b2[l],
            p_fh);
    }

    // ---- pool + head ----
    pool_seg_kernel<<<N_GRAPHS, 128>>>(p_fh, p_pool);
    head_kernel<<<N_GRAPHS, 128>>>(p_pool, l1w, l1b, l2w, l2b, out);
}